// round 13
// baseline (speedup 1.0000x reference)
#include <cuda_runtime.h>
#include <cstdint>
#include <math.h>

// ---------------- problem constants ----------------
#define BATCH 2
#define SEQ   2048
#define DMODEL 2048
#define NHEAD 16
#define HDIM  128
#define RQ    1536
#define RKV   512
#define MTOT  (BATCH*SEQ)          // 4096

// ---------------- scratch (allocation-free: __device__ globals) ----------------
__device__ float g_xq[(size_t)MTOT * RQ];            // X @ Wq_down^T (tf32-rounded)
__device__ float g_q [(size_t)MTOT * DMODEL];        // Q (tf32-rounded)
__device__ float g_c [(size_t)MTOT * RKV];           // latent C (tf32-rounded)
__device__ float g_k [(size_t)BATCH*NHEAD*SEQ*HDIM]; // K (tf32-rounded)
__device__ float g_v [(size_t)BATCH*NHEAD*SEQ*HDIM]; // V (tf32-rounded)
__device__ float g_o [(size_t)MTOT * DMODEL];        // attn out (tf32-rounded)
__device__ float g_kuT[(size_t)NHEAD*HDIM*RKV];      // k_up^T (tf32-rounded)
__device__ float g_vuT[(size_t)NHEAD*HDIM*RKV];      // v_up^T (tf32-rounded)
// tf32-rounded copies of raw inputs
__device__ float g_xr  [(size_t)MTOT * DMODEL];
__device__ float g_wqdr[(size_t)RQ * DMODEL];
__device__ float g_wqur[(size_t)DMODEL * RQ];
__device__ float g_wkdr[(size_t)RKV * DMODEL];
__device__ float g_wor [(size_t)DMODEL * DMODEL];

// ---------------- helpers ----------------
__device__ __forceinline__ uint32_t smem_u32(const void* p) {
    uint32_t a;
    asm("{ .reg .u64 t; cvta.to.shared.u64 t, %1; cvt.u32.u64 %0, t; }" : "=r"(a) : "l"(p));
    return a;
}
__device__ __forceinline__ uint32_t f2tf32(float x) {
    uint32_t r;
    asm("cvt.rna.tf32.f32 %0, %1;" : "=r"(r) : "f"(x));
    return r;
}
__device__ __forceinline__ float f2tf32f(float x) { return __uint_as_float(f2tf32(x)); }
__device__ __forceinline__ void cp16(uint32_t saddr, const void* gaddr) {
    asm volatile("cp.async.cg.shared.global [%0], [%1], 16;" :: "r"(saddr), "l"(gaddr));
}
#define CP_COMMIT()  asm volatile("cp.async.commit_group;" ::: "memory")
#define CP_WAIT_1()  asm volatile("cp.async.wait_group 1;" ::: "memory")
#define CP_WAIT_0()  asm volatile("cp.async.wait_group 0;" ::: "memory")

// ldmatrix x4: four 8x(16B) matrices; for tf32 fragments lane L <- (row L/4, word L%4).
__device__ __forceinline__ void ldsm4(uint32_t& r0, uint32_t& r1, uint32_t& r2, uint32_t& r3,
                                      uint32_t saddr) {
    asm volatile("ldmatrix.sync.aligned.m8n8.x4.shared.b16 {%0,%1,%2,%3}, [%4];"
                 : "=r"(r0), "=r"(r1), "=r"(r2), "=r"(r3) : "r"(saddr));
}

// mma.sync m16n8k8 tf32: D = A(16x8 row) * B(8x8 col) + C, fp32 accum.
__device__ __forceinline__ void mma_tf32(float& c0, float& c1, float& c2, float& c3,
                                         uint32_t a0, uint32_t a1, uint32_t a2, uint32_t a3,
                                         uint32_t b0, uint32_t b1) {
    asm volatile(
        "mma.sync.aligned.m16n8k8.row.col.f32.tf32.tf32.f32 "
        "{%0,%1,%2,%3}, {%4,%5,%6,%7}, {%8,%9}, {%0,%1,%2,%3};"
        : "+f"(c0), "+f"(c1), "+f"(c2), "+f"(c3)
        : "r"(a0), "r"(a1), "r"(a2), "r"(a3), "r"(b0), "r"(b1));
}

// ---------------- elementwise tf32 rounding copy ----------------
__global__ __launch_bounds__(256)
void round_tf32(const float* __restrict__ in, float* __restrict__ out, long n4)
{
    long i = (long)blockIdx.x * blockDim.x + threadIdx.x;
    long stride = (long)gridDim.x * blockDim.x;
    for (; i < n4; i += stride) {
        float4 v = ((const float4*)in)[i];
        v.x = f2tf32f(v.x); v.y = f2tf32f(v.y); v.z = f2tf32f(v.z); v.w = f2tf32f(v.w);
        ((float4*)out)[i] = v;
    }
}

// ---------------- tf32 tensor-core GEMM: C = A @ B^T (cp.async + ldmatrix) ----------------
// ALL inputs must be tf32-valued fp32 in gmem (pre-rounded) -> no cvt anywhere.
// A [M,K] row-major, B [N,K] row-major. M%128==0, N%128==0, K%32==0.
// CTA 128x128, BK=32, 128 threads = 4 warps, warp tile 64x64 (4x8 of m16n8k8).
// Fragments via ldmatrix.x4: per k8-step 8 LDSM + 32 MMA.
// RND: round outputs to tf32 (for tensors consumed by later mma stages).
#define BK 32
#define ST 36                       // row stride in words (32 + 4 pad): LDSM phases conflict-free
#define GEMM_BUF_WORDS (128 * ST)   // 4608 words per tile buffer
#define GEMM_SMEM_BYTES (4 * GEMM_BUF_WORDS * 4)   // A0,B0,A1,B1 = 73728 B

template<bool RND>
__global__ __launch_bounds__(128, 2)
void gemm_tc(const float* __restrict__ A, const float* __restrict__ B,
             float* __restrict__ C, int M, int N, int K,
             long sA, long sB, long sC, int hmod)
{
    extern __shared__ uint32_t sh[];
    const uint32_t sbase = smem_u32(sh);

    const int tid = threadIdx.x;
    const int wid = tid >> 5, lane = tid & 31;
    const int g = lane >> 2, t = lane & 3;           // groupID / threadID_in_group
    const int quad = lane >> 3, rin = lane & 7;      // ldmatrix lane mapping
    const int z = blockIdx.z;
    const float* Ab = A + (long)(z / hmod) * sA;
    const float* Bb = B + (long)(z % hmod) * sB;
    float* Cb = C + (long)z * sC;
    const int m0 = blockIdx.y * 128;
    const int n0 = blockIdx.x * 128;

    const int wm = (wid & 1) * 64;                   // warp tile origin in M
    const int wn = (wid >> 1) * 64;                  // warp tile origin in N

    // per-thread ldmatrix base offsets (words)
    const uint32_t aoff_t = (uint32_t)((wm + (quad & 1) * 8 + rin) * ST + (quad >> 1) * 4);
    const uint32_t boff_t = (uint32_t)((wn + (quad >> 1) * 8 + rin) * ST + (quad & 1) * 4);

    float acc[4][8][4];
    #pragma unroll
    for (int m = 0; m < 4; m++)
        #pragma unroll
        for (int n = 0; n < 8; n++)
            #pragma unroll
            for (int r = 0; r < 4; r++) acc[m][n][r] = 0.f;

    const int lrow = tid >> 3;          // 0..15
    const int lc4  = (tid & 7) << 2;    // 0,4,..,28

    auto issue = [&](int k0, int b) {
        const uint32_t abase = sbase + (uint32_t)b * (2u * GEMM_BUF_WORDS * 4u);
        const uint32_t bbase = abase + GEMM_BUF_WORDS * 4u;
        #pragma unroll
        for (int p = 0; p < 8; p++) {
            const int row = lrow + p * 16;
            const uint32_t so = (uint32_t)(row * ST + lc4) * 4u;
            cp16(abase + so, Ab + (long)(m0 + row) * K + k0 + lc4);
            cp16(bbase + so, Bb + (long)(n0 + row) * K + k0 + lc4);
        }
        CP_COMMIT();
    };

    const int KT = K >> 5;
    issue(0, 0);

    for (int kt = 0; kt < KT; kt++) {
        if (kt + 1 < KT) { issue((kt + 1) << 5, (kt + 1) & 1); CP_WAIT_1(); }
        else             { CP_WAIT_0(); }
        __syncthreads();

        const uint32_t abuf = sbase + (uint32_t)(kt & 1) * (2u * GEMM_BUF_WORDS * 4u);
        const uint32_t bbuf = abuf + GEMM_BUF_WORDS * 4u;
        const uint32_t aaddr = abuf + aoff_t * 4u;
        const uint32_t baddr = bbuf + boff_t * 4u;

        #pragma unroll
        for (int ks = 0; ks < BK / 8; ks++) {
            const uint32_t kk = (uint32_t)(ks * 8);
            uint32_t af[4][4], bf[8][2];
            #pragma unroll
            for (int m = 0; m < 4; m++)
                ldsm4(af[m][0], af[m][1], af[m][2], af[m][3],
                      aaddr + (uint32_t)(m * 16 * ST + kk) * 4u);
            #pragma unroll
            for (int np = 0; np < 4; np++)
                ldsm4(bf[2*np][0], bf[2*np][1], bf[2*np+1][0], bf[2*np+1][1],
                      baddr + (uint32_t)(np * 16 * ST + kk) * 4u);
            #pragma unroll
            for (int m = 0; m < 4; m++)
                #pragma unroll
                for (int n = 0; n < 8; n++)
                    mma_tf32(acc[m][n][0], acc[m][n][1], acc[m][n][2], acc[m][n][3],
                             af[m][0], af[m][1], af[m][2], af[m][3],
                             bf[n][0], bf[n][1]);
        }
        __syncthreads();
    }

    #pragma unroll
    for (int m = 0; m < 4; m++) {
        const long row0 = m0 + wm + m * 16 + g;
        #pragma unroll
        for (int n = 0; n < 8; n++) {
            const int col = n0 + wn + n * 8 + 2 * t;
            float v0 = acc[m][n][0], v1 = acc[m][n][1];
            float v2 = acc[m][n][2], v3 = acc[m][n][3];
            if (RND) {
                v0 = f2tf32f(v0); v1 = f2tf32f(v1);
                v2 = f2tf32f(v2); v3 = f2tf32f(v3);
            }
            *(float2*)(Cb + row0 * N + col)       = make_float2(v0, v1);
            *(float2*)(Cb + (row0 + 8) * N + col) = make_float2(v2, v3);
        }
    }
}

// ---------------- transpose [H, RKV, HDIM] -> [H, HDIM, RKV], tf32-round on store ----------------
__global__ __launch_bounds__(256)
void transpose_up(const float* __restrict__ in, float* __restrict__ out)
{
    __shared__ float t[32][33];
    const int h = blockIdx.z;
    const int r0 = blockIdx.y * 32;   // RKV dim
    const int c0 = blockIdx.x * 32;   // HDIM dim
    const int tx = threadIdx.x & 31, ty0 = threadIdx.x >> 5;
    const float* ip = in + (long)h * RKV * HDIM;
    float* op = out + (long)h * RKV * HDIM;
    #pragma unroll
    for (int r = 0; r < 4; r++) {
        int ty = ty0 + r * 8;
        t[ty][tx] = ip[(long)(r0 + ty) * HDIM + c0 + tx];
    }
    __syncthreads();
    #pragma unroll
    for (int r = 0; r < 4; r++) {
        int ty = ty0 + r * 8;
        op[(long)(c0 + ty) * RKV + r0 + tx] = f2tf32f(t[tx][ty]);
    }
}

// ---------------- tensor-core flash attention (tf32 mma, ALiBi + causal) ----------------
// BM=64 q-rows/CTA, BN=64 kv per iter, d=128. 256 threads, 8 warps.
// Q/K/V tf32-rounded by producers -> raw bits feed mma directly.
// Q/K/P fragments via ldmatrix (same mapping validated in gemm_tc); V stays scalar LDS
// (transposed access; ldmatrix.trans is b16-only).
// cp.async double-buffered K/V pipeline; cross-warp row softmax via smem Red/Sum.
#define FQS 132
#define FVS 136
#define FPS 68
#define F_KOFF   (64*FQS)
#define F_VOFF   (F_KOFF + 2*64*FQS)
#define F_POFF   (F_VOFF + 2*64*FVS)
#define F_ROFF   (F_POFF + 64*FPS)
#define FLASH_SMEM_WORDS (F_ROFF + 256)
#define FLASH_SMEM_BYTES (FLASH_SMEM_WORDS * 4)     // 189440 B

__global__ __launch_bounds__(256)
void flash_tc(const float* __restrict__ Q, const float* __restrict__ Kg,
              const float* __restrict__ Vg, float* __restrict__ O)
{
    extern __shared__ uint32_t sm[];
    const uint32_t sbase = smem_u32(sm);
    uint32_t* Ps = sm + F_POFF;                     // [64][68] tf32
    float*    Red = (float*)(sm + F_ROFF);          // [2][64] partial max
    float*    Sum = Red + 128;                      // [2][64] partial sum

    const int bh = blockIdx.y;
    const int b  = bh >> 4, h = bh & 15;
    const int qt = blockIdx.x;
    const int q0 = qt * 64;
    const int tid = threadIdx.x;
    const int wid = tid >> 5, lane = tid & 31;
    const int g = lane >> 2, t = lane & 3;
    const int quad = lane >> 3, rin = lane & 7;     // ldmatrix lane mapping
    const int mw = wid & 3;                   // M strip (16 rows)
    const int nw = wid >> 2;                  // N strip

    const float slope = exp2f(-0.5f * (float)(h + 1));
    const float scale = 0.08838834764831843f;

    const float* Qbase = Q  + ((long)(b*SEQ + q0)) * DMODEL + h*HDIM;
    const float* Kbase = Kg + ((long)(b*NHEAD + h)) * SEQ * HDIM;
    const float* Vbase = Vg + ((long)(b*NHEAD + h)) * SEQ * HDIM;

    auto issueK = [&](int k0, int buf) {
        const uint32_t base = sbase + (uint32_t)(F_KOFF + buf * 64 * FQS) * 4u;
        #pragma unroll
        for (int p = 0; p < 8; p++) {
            int idx = tid + p*256;
            int row = idx >> 5, c4 = (idx & 31) << 2;
            cp16(base + (uint32_t)(row*FQS + c4)*4u, Kbase + (long)(k0+row)*HDIM + c4);
        }
    };
    auto issueV = [&](int k0, int buf) {
        const uint32_t base = sbase + (uint32_t)(F_VOFF + buf * 64 * FVS) * 4u;
        #pragma unroll
        for (int p = 0; p < 8; p++) {
            int idx = tid + p*256;
            int row = idx >> 5, c4 = (idx & 31) << 2;
            cp16(base + (uint32_t)(row*FVS + c4)*4u, Vbase + (long)(k0+row)*HDIM + c4);
        }
    };

    // prefetch group 0: Q tile + K0 + V0
    #pragma unroll
    for (int p = 0; p < 8; p++) {
        int idx = tid + p*256;
        int row = idx >> 5, c4 = (idx & 31) << 2;
        cp16(sbase + (uint32_t)(row*FQS + c4)*4u, Qbase + (long)row*DMODEL + c4);
    }
    issueK(0, 0); issueV(0, 0);
    CP_COMMIT();

    const int r0 = mw*16 + g, r1 = r0 + 8;    // this thread's q rows (local)
    const int qi0 = q0 + r0, qi1 = q0 + r1;

    // ldmatrix per-thread base offsets (words)
    const uint32_t qoff_t = (uint32_t)((mw*16 + (quad & 1) * 8 + rin) * FQS + (quad >> 1) * 4);
    const uint32_t koff_t = (uint32_t)((nw*32 + (quad >> 1) * 8 + rin) * FQS + (quad & 1) * 4);
    const uint32_t poff_t = (uint32_t)((mw*16 + (quad & 1) * 8 + rin) * FPS + (quad >> 1) * 4);
    const uint32_t qaddr  = sbase + qoff_t * 4u;
    const uint32_t paddr  = sbase + (uint32_t)F_POFF * 4u + poff_t * 4u;

    float o[8][4];
    #pragma unroll
    for (int n = 0; n < 8; n++)
        #pragma unroll
        for (int r = 0; r < 4; r++) o[n][r] = 0.f;
    float m0 = -INFINITY, m1 = -INFINITY, l0 = 0.f, l1 = 0.f;

    for (int kt = 0; kt <= qt; kt++) {
        const int k0 = kt * 64;
        __syncthreads();   // (a) all warps done with prev iteration -> buf (kt+1)&1 free
        if (kt < qt) {
            issueK(k0 + 64, (kt + 1) & 1);
            issueV(k0 + 64, (kt + 1) & 1);
            CP_COMMIT();
            CP_WAIT_1();   // K(kt),V(kt) (+Q at kt=0) complete
        } else {
            CP_WAIT_0();
        }
        __syncthreads();   // (c) visibility of completed copies to all warps

        const uint32_t kaddr = sbase + (uint32_t)(F_KOFF + (kt & 1) * 64 * FQS) * 4u + koff_t * 4u;
        const uint32_t* Vb = sm + F_VOFF + (size_t)(kt & 1) * (64 * FVS);

        // S = Q @ K^T  (warp tile 16x32: 4 n-subtiles) via ldmatrix
        float s[4][4];
        #pragma unroll
        for (int n = 0; n < 4; n++)
            #pragma unroll
            for (int r = 0; r < 4; r++) s[n][r] = 0.f;
        #pragma unroll
        for (int ks = 0; ks < 16; ks++) {
            const uint32_t kk = (uint32_t)(ks * 8);
            uint32_t a0, a1, a2, a3;
            ldsm4(a0, a1, a2, a3, qaddr + kk * 4u);
            uint32_t bf[4][2];
            ldsm4(bf[0][0], bf[0][1], bf[1][0], bf[1][1], kaddr + kk * 4u);
            ldsm4(bf[2][0], bf[2][1], bf[3][0], bf[3][1], kaddr + (uint32_t)(16 * FQS) * 4u + kk * 4u);
            #pragma unroll
            for (int n = 0; n < 4; n++)
                mma_tf32(s[n][0], s[n][1], s[n][2], s[n][3], a0, a1, a2, a3,
                         bf[n][0], bf[n][1]);
        }

        // scale + ALiBi + causal, partial (this warp's 32-col half) row max
        float rv0 = -INFINITY, rv1 = -INFINITY;
        #pragma unroll
        for (int n = 0; n < 4; n++) {
            const int kj = k0 + nw*32 + n*8 + 2*t;
            s[n][0] = (kj   <= qi0) ? fmaf(s[n][0], scale, -slope*(float)(qi0-kj))   : -INFINITY;
            s[n][1] = (kj+1 <= qi0) ? fmaf(s[n][1], scale, -slope*(float)(qi0-kj-1)) : -INFINITY;
            s[n][2] = (kj   <= qi1) ? fmaf(s[n][2], scale, -slope*(float)(qi1-kj))   : -INFINITY;
            s[n][3] = (kj+1 <= qi1) ? fmaf(s[n][3], scale, -slope*(float)(qi1-kj-1)) : -INFINITY;
            rv0 = fmaxf(rv0, fmaxf(s[n][0], s[n][1]));
            rv1 = fmaxf(rv1, fmaxf(s[n][2], s[n][3]));
        }
        rv0 = fmaxf(rv0, __shfl_xor_sync(0xffffffffu, rv0, 1));
        rv0 = fmaxf(rv0, __shfl_xor_sync(0xffffffffu, rv0, 2));
        rv1 = fmaxf(rv1, __shfl_xor_sync(0xffffffffu, rv1, 1));
        rv1 = fmaxf(rv1, __shfl_xor_sync(0xffffffffu, rv1, 2));
        if (t == 0) { Red[nw*64 + r0] = rv0; Red[nw*64 + r1] = rv1; }
        __syncthreads();   // (e) partial maxes visible

        // combined (full-row) max -> consistent softmax across both warp halves
        rv0 = fmaxf(Red[r0], Red[64 + r0]);
        rv1 = fmaxf(Red[r1], Red[64 + r1]);
        const float m0n = fmaxf(m0, rv0), m1n = fmaxf(m1, rv1);
        const float al0 = __expf(m0 - m0n), al1 = __expf(m1 - m1n);
        m0 = m0n; m1 = m1n;
        float rs0 = 0.f, rs1 = 0.f;
        #pragma unroll
        for (int n = 0; n < 4; n++) {
            float p00 = __expf(s[n][0] - m0n), p01 = __expf(s[n][1] - m0n);
            float p10 = __expf(s[n][2] - m1n), p11 = __expf(s[n][3] - m1n);
            rs0 += p00 + p01; rs1 += p10 + p11;
            const int cn = nw*32 + n*8 + 2*t;
            Ps[r0*FPS + cn] = f2tf32(p00); Ps[r0*FPS + cn + 1] = f2tf32(p01);
            Ps[r1*FPS + cn] = f2tf32(p10); Ps[r1*FPS + cn + 1] = f2tf32(p11);
        }
        rs0 += __shfl_xor_sync(0xffffffffu, rs0, 1);
        rs0 += __shfl_xor_sync(0xffffffffu, rs0, 2);
        rs1 += __shfl_xor_sync(0xffffffffu, rs1, 1);
        rs1 += __shfl_xor_sync(0xffffffffu, rs1, 2);
        if (t == 0) { Sum[nw*64 + r0] = rs0; Sum[nw*64 + r1] = rs1; }
        __syncthreads();   // (g) Ps + partial sums complete

        // combined row sum; update l and rescale o
        rs0 = Sum[r0] + Sum[64 + r0];
        rs1 = Sum[r1] + Sum[64 + r1];
        l0 = l0 * al0 + rs0; l1 = l1 * al1 + rs1;
        #pragma unroll
        for (int n = 0; n < 8; n++) {
            o[n][0] *= al0; o[n][1] *= al0; o[n][2] *= al1; o[n][3] *= al1;
        }

        // O += P @ V  (warp tile 16x64: 8 d-subtiles); P via ldmatrix, V scalar
        #pragma unroll
        for (int ks = 0; ks < 8; ks++) {
            const uint32_t kk = (uint32_t)(ks * 8);
            uint32_t a0, a1, a2, a3;
            ldsm4(a0, a1, a2, a3, paddr + kk * 4u);
            #pragma unroll
            for (int n = 0; n < 8; n++) {
                const int col = nw*64 + n*8 + g;
                uint32_t b0 = Vb[(ks*8 + t)*FVS + col];
                uint32_t b1 = Vb[(ks*8 + t + 4)*FVS + col];
                mma_tf32(o[n][0], o[n][1], o[n][2], o[n][3], a0, a1, a2, a3, b0, b1);
            }
        }
    }

    // normalize + tf32-round + write O[b, q, h*128 + col]
    const float inv0 = 1.f / l0, inv1 = 1.f / l1;
    const long row0 = (long)(b*SEQ + q0 + r0);
    const long row1 = (long)(b*SEQ + q0 + r1);
    #pragma unroll
    for (int n = 0; n < 8; n++) {
        const int col = h*HDIM + nw*64 + n*8 + 2*t;
        *(float2*)(O + row0*DMODEL + col) = make_float2(f2tf32f(o[n][0]*inv0), f2tf32f(o[n][1]*inv0));
        *(float2*)(O + row1*DMODEL + col) = make_float2(f2tf32f(o[n][2]*inv1), f2tf32f(o[n][3]*inv1));
    }
}

// ---------------- launch ----------------
extern "C" void kernel_launch(void* const* d_in, const int* in_sizes, int n_in,
                              void* d_out, int out_size)
{
    const float* X        = (const float*)d_in[0];
    const float* Wq_down  = (const float*)d_in[1];   // [1536, 2048]
    const float* Wq_up    = (const float*)d_in[2];   // [2048, 1536]
    const float* Wkv_down = (const float*)d_in[3];   // [512, 2048]
    const float* k_up     = (const float*)d_in[4];   // [16, 512, 128]
    const float* v_up     = (const float*)d_in[5];   // [16, 512, 128]
    const float* Wo       = (const float*)d_in[6];   // [2048, 2048]
    float* out = (float*)d_out;

    float *xq, *q, *c, *kb, *vb, *ob, *kuT, *vuT;
    float *xr, *wqdr, *wqur, *wkdr, *wor;
    cudaGetSymbolAddress((void**)&xq,  g_xq);
    cudaGetSymbolAddress((void**)&q,   g_q);
    cudaGetSymbolAddress((void**)&c,   g_c);
    cudaGetSymbolAddress((void**)&kb,  g_k);
    cudaGetSymbolAddress((void**)&vb,  g_v);
    cudaGetSymbolAddress((void**)&ob,  g_o);
    cudaGetSymbolAddress((void**)&kuT, g_kuT);
    cudaGetSymbolAddress((void**)&vuT, g_vuT);
    cudaGetSymbolAddress((void**)&xr,   g_xr);
    cudaGetSymbolAddress((void**)&wqdr, g_wqdr);
    cudaGetSymbolAddress((void**)&wqur, g_wqur);
    cudaGetSymbolAddress((void**)&wkdr, g_wkdr);
    cudaGetSymbolAddress((void**)&wor,  g_wor);

    cudaFuncSetAttribute(gemm_tc<false>,
                         cudaFuncAttributeMaxDynamicSharedMemorySize, GEMM_SMEM_BYTES);
    cudaFuncSetAttribute(gemm_tc<true>,
                         cudaFuncAttributeMaxDynamicSharedMemorySize, GEMM_SMEM_BYTES);
    cudaFuncSetAttribute(gemm_tc<false>,
                         cudaFuncAttributePreferredSharedMemoryCarveout, 100);
    cudaFuncSetAttribute(gemm_tc<true>,
                         cudaFuncAttributePreferredSharedMemoryCarveout, 100);
    cudaFuncSetAttribute(flash_tc,
                         cudaFuncAttributeMaxDynamicSharedMemorySize, FLASH_SMEM_BYTES);

    dim3 blk(256);
    dim3 blkG(128);

    // 0) tf32-round all raw GEMM inputs (one-time copies)
    round_tf32<<<512, blk>>>(X,        xr,   (long)MTOT*DMODEL/4);
    round_tf32<<<512, blk>>>(Wq_down,  wqdr, (long)RQ*DMODEL/4);
    round_tf32<<<512, blk>>>(Wq_up,    wqur, (long)DMODEL*RQ/4);
    round_tf32<<<512, blk>>>(Wkv_down, wkdr, (long)RKV*DMODEL/4);
    round_tf32<<<512, blk>>>(Wo,       wor,  (long)DMODEL*DMODEL/4);
    transpose_up<<<dim3(HDIM/32, RKV/32, NHEAD), blk>>>(k_up, kuT);
    transpose_up<<<dim3(HDIM/32, RKV/32, NHEAD), blk>>>(v_up, vuT);

    // 1) Xq = X @ Wq_down^T : [4096,1536]  (rounded: feeds GEMM 2)
    gemm_tc<true><<<dim3(RQ/128, MTOT/128, 1), blkG, GEMM_SMEM_BYTES>>>(
        xr, wqdr, xq, MTOT, RQ, DMODEL, 0, 0, 0, 1);
    // 2) Q = Xq @ Wq_up^T : [4096,2048]  (rounded: feeds flash)
    gemm_tc<true><<<dim3(DMODEL/128, MTOT/128, 1), blkG, GEMM_SMEM_BYTES>>>(
        xq, wqur, q, MTOT, DMODEL, RQ, 0, 0, 0, 1);
    // 3) C = X @ Wkv_down^T : [4096,512]  (rounded: feeds GEMMs 4,5)
    gemm_tc<true><<<dim3(RKV/128, MTOT/128, 1), blkG, GEMM_SMEM_BYTES>>>(
        xr, wkdr, c, MTOT, RKV, DMODEL, 0, 0, 0, 1);
    // 4) K[b,h] = C_b @ kuT[h]^T : batched 32x [2048,128]  (rounded)
    gemm_tc<true><<<dim3(1, SEQ/128, BATCH*NHEAD), blkG, GEMM_SMEM_BYTES>>>(
        c, kuT, kb, SEQ, HDIM, RKV,
        (long)SEQ*RKV, (long)HDIM*RKV, (long)SEQ*HDIM, NHEAD);
    // 5) V likewise (rounded)
    gemm_tc<true><<<dim3(1, SEQ/128, BATCH*NHEAD), blkG, GEMM_SMEM_BYTES>>>(
        c, vuT, vb, SEQ, HDIM, RKV,
        (long)SEQ*RKV, (long)HDIM*RKV, (long)SEQ*HDIM, NHEAD);
    // 6) tensor-core causal+ALiBi flash attention -> ob (rounded on store)
    flash_tc<<<dim3(SEQ/64, BATCH*NHEAD), blk, FLASH_SMEM_BYTES>>>(q, kb, vb, ob);
    // 7) out = ob @ Wo^T : [4096,2048]  (NOT rounded: final output)
    gemm_tc<false><<<dim3(DMODEL/128, MTOT/128, 1), blkG, GEMM_SMEM_BYTES>>>(
        ob, wor, out, MTOT, DMODEL, DMODEL, 0, 0, 0, 1);
}

// round 14
// speedup vs baseline: 1.5524x; 1.5524x over previous
#include <cuda_runtime.h>
#include <cstdint>
#include <math.h>

// ---------------- problem constants ----------------
#define BATCH 2
#define SEQ   2048
#define DMODEL 2048
#define NHEAD 16
#define HDIM  128
#define RQ    1536
#define RKV   512
#define MTOT  (BATCH*SEQ)          // 4096

// ---------------- scratch (allocation-free: __device__ globals) ----------------
__device__ float g_xq[(size_t)MTOT * RQ];            // X @ Wq_down^T (tf32-rounded)
__device__ float g_q [(size_t)MTOT * DMODEL];        // Q (tf32-rounded)
__device__ float g_c [(size_t)MTOT * RKV];           // latent C (tf32-rounded)
__device__ float g_k [(size_t)BATCH*NHEAD*SEQ*HDIM]; // K (tf32-rounded)
__device__ float g_v [(size_t)BATCH*NHEAD*SEQ*HDIM]; // V (tf32-rounded)
__device__ float g_o [(size_t)MTOT * DMODEL];        // attn out (tf32-rounded)
__device__ float g_kuT[(size_t)NHEAD*HDIM*RKV];      // k_up^T (tf32-rounded)
__device__ float g_vuT[(size_t)NHEAD*HDIM*RKV];      // v_up^T (tf32-rounded)
// tf32-rounded copies of raw inputs
__device__ float g_xr  [(size_t)MTOT * DMODEL];
__device__ float g_wqdr[(size_t)RQ * DMODEL];
__device__ float g_wqur[(size_t)DMODEL * RQ];
__device__ float g_wkdr[(size_t)RKV * DMODEL];
__device__ float g_wor [(size_t)DMODEL * DMODEL];

// ---------------- helpers ----------------
__device__ __forceinline__ uint32_t smem_u32(const void* p) {
    uint32_t a;
    asm("{ .reg .u64 t; cvta.to.shared.u64 t, %1; cvt.u32.u64 %0, t; }" : "=r"(a) : "l"(p));
    return a;
}
__device__ __forceinline__ uint32_t f2tf32(float x) {
    uint32_t r;
    asm("cvt.rna.tf32.f32 %0, %1;" : "=r"(r) : "f"(x));
    return r;
}
__device__ __forceinline__ float f2tf32f(float x) { return __uint_as_float(f2tf32(x)); }
__device__ __forceinline__ void cp16(uint32_t saddr, const void* gaddr) {
    asm volatile("cp.async.cg.shared.global [%0], [%1], 16;" :: "r"(saddr), "l"(gaddr));
}
#define CP_COMMIT()  asm volatile("cp.async.commit_group;" ::: "memory")
#define CP_WAIT_1()  asm volatile("cp.async.wait_group 1;" ::: "memory")
#define CP_WAIT_0()  asm volatile("cp.async.wait_group 0;" ::: "memory")

// ldmatrix x4: four 8x(16B) matrices; for tf32 fragments lane L <- (row L/4, word L%4).
__device__ __forceinline__ void ldsm4(uint32_t& r0, uint32_t& r1, uint32_t& r2, uint32_t& r3,
                                      uint32_t saddr) {
    asm volatile("ldmatrix.sync.aligned.m8n8.x4.shared.b16 {%0,%1,%2,%3}, [%4];"
                 : "=r"(r0), "=r"(r1), "=r"(r2), "=r"(r3) : "r"(saddr));
}

// mma.sync m16n8k8 tf32: D = A(16x8 row) * B(8x8 col) + C, fp32 accum.
__device__ __forceinline__ void mma_tf32(float& c0, float& c1, float& c2, float& c3,
                                         uint32_t a0, uint32_t a1, uint32_t a2, uint32_t a3,
                                         uint32_t b0, uint32_t b1) {
    asm volatile(
        "mma.sync.aligned.m16n8k8.row.col.f32.tf32.tf32.f32 "
        "{%0,%1,%2,%3}, {%4,%5,%6,%7}, {%8,%9}, {%0,%1,%2,%3};"
        : "+f"(c0), "+f"(c1), "+f"(c2), "+f"(c3)
        : "r"(a0), "r"(a1), "r"(a2), "r"(a3), "r"(b0), "r"(b1));
}

// ---------------- elementwise tf32 rounding copy ----------------
__global__ __launch_bounds__(256)
void round_tf32(const float* __restrict__ in, float* __restrict__ out, long n4)
{
    long i = (long)blockIdx.x * blockDim.x + threadIdx.x;
    long stride = (long)gridDim.x * blockDim.x;
    for (; i < n4; i += stride) {
        float4 v = ((const float4*)in)[i];
        v.x = f2tf32f(v.x); v.y = f2tf32f(v.y); v.z = f2tf32f(v.z); v.w = f2tf32f(v.w);
        ((float4*)out)[i] = v;
    }
}

// ---------------- tf32 tensor-core GEMM: C = A @ B^T (cp.async + ldmatrix) ----------------
// ALL inputs must be tf32-valued fp32 in gmem (pre-rounded) -> no cvt anywhere.
// A [M,K] row-major, B [N,K] row-major. M%128==0, N%128==0, K%32==0.
// CTA 128x128, BK=32, 128 threads = 4 warps, warp tile 64x64 (4x8 of m16n8k8).
// Fragments via ldmatrix.x4: per k8-step 8 LDSM + 32 MMA.
// Dual-output batching: z >= nz1 switches to (B2, C2) with z -= nz1 (for merged K/V GEMMs).
// RND: round outputs to tf32 (for tensors consumed by later mma stages).
#define BK 32
#define ST 36                       // row stride in words (32 + 4 pad): LDSM phases conflict-free
#define GEMM_BUF_WORDS (128 * ST)   // 4608 words per tile buffer
#define GEMM_SMEM_BYTES (4 * GEMM_BUF_WORDS * 4)   // A0,B0,A1,B1 = 73728 B

template<bool RND>
__global__ __launch_bounds__(128, 2)
void gemm_tc(const float* __restrict__ A, const float* __restrict__ B,
             float* __restrict__ C,
             const float* __restrict__ B2, float* __restrict__ C2, int nz1,
             int M, int N, int K,
             long sA, long sB, long sC, int hmod)
{
    extern __shared__ uint32_t sh[];
    const uint32_t sbase = smem_u32(sh);

    const int tid = threadIdx.x;
    const int wid = tid >> 5, lane = tid & 31;
    const int g = lane >> 2, t = lane & 3;           // groupID / threadID_in_group
    const int quad = lane >> 3, rin = lane & 7;      // ldmatrix lane mapping
    int z = blockIdx.z;
    const float* Bp = B;
    float* Cp = C;
    if (z >= nz1) { Bp = B2; Cp = C2; z -= nz1; }
    const float* Ab = A + (long)(z / hmod) * sA;
    const float* Bb = Bp + (long)(z % hmod) * sB;
    float* Cb = Cp + (long)z * sC;
    const int m0 = blockIdx.y * 128;
    const int n0 = blockIdx.x * 128;

    const int wm = (wid & 1) * 64;                   // warp tile origin in M
    const int wn = (wid >> 1) * 64;                  // warp tile origin in N

    // per-thread ldmatrix base offsets (words)
    const uint32_t aoff_t = (uint32_t)((wm + (quad & 1) * 8 + rin) * ST + (quad >> 1) * 4);
    const uint32_t boff_t = (uint32_t)((wn + (quad >> 1) * 8 + rin) * ST + (quad & 1) * 4);

    float acc[4][8][4];
    #pragma unroll
    for (int m = 0; m < 4; m++)
        #pragma unroll
        for (int n = 0; n < 8; n++)
            #pragma unroll
            for (int r = 0; r < 4; r++) acc[m][n][r] = 0.f;

    const int lrow = tid >> 3;          // 0..15
    const int lc4  = (tid & 7) << 2;    // 0,4,..,28

    auto issue = [&](int k0, int b) {
        const uint32_t abase = sbase + (uint32_t)b * (2u * GEMM_BUF_WORDS * 4u);
        const uint32_t bbase = abase + GEMM_BUF_WORDS * 4u;
        #pragma unroll
        for (int p = 0; p < 8; p++) {
            const int row = lrow + p * 16;
            const uint32_t so = (uint32_t)(row * ST + lc4) * 4u;
            cp16(abase + so, Ab + (long)(m0 + row) * K + k0 + lc4);
            cp16(bbase + so, Bb + (long)(n0 + row) * K + k0 + lc4);
        }
        CP_COMMIT();
    };

    const int KT = K >> 5;
    issue(0, 0);

    for (int kt = 0; kt < KT; kt++) {
        if (kt + 1 < KT) { issue((kt + 1) << 5, (kt + 1) & 1); CP_WAIT_1(); }
        else             { CP_WAIT_0(); }
        __syncthreads();

        const uint32_t abuf = sbase + (uint32_t)(kt & 1) * (2u * GEMM_BUF_WORDS * 4u);
        const uint32_t bbuf = abuf + GEMM_BUF_WORDS * 4u;
        const uint32_t aaddr = abuf + aoff_t * 4u;
        const uint32_t baddr = bbuf + boff_t * 4u;

        #pragma unroll
        for (int ks = 0; ks < BK / 8; ks++) {
            const uint32_t kk = (uint32_t)(ks * 8);
            uint32_t af[4][4], bf[8][2];
            #pragma unroll
            for (int m = 0; m < 4; m++)
                ldsm4(af[m][0], af[m][1], af[m][2], af[m][3],
                      aaddr + (uint32_t)(m * 16 * ST + kk) * 4u);
            #pragma unroll
            for (int np = 0; np < 4; np++)
                ldsm4(bf[2*np][0], bf[2*np][1], bf[2*np+1][0], bf[2*np+1][1],
                      baddr + (uint32_t)(np * 16 * ST + kk) * 4u);
            #pragma unroll
            for (int m = 0; m < 4; m++)
                #pragma unroll
                for (int n = 0; n < 8; n++)
                    mma_tf32(acc[m][n][0], acc[m][n][1], acc[m][n][2], acc[m][n][3],
                             af[m][0], af[m][1], af[m][2], af[m][3],
                             bf[n][0], bf[n][1]);
        }
        __syncthreads();
    }

    #pragma unroll
    for (int m = 0; m < 4; m++) {
        const long row0 = m0 + wm + m * 16 + g;
        #pragma unroll
        for (int n = 0; n < 8; n++) {
            const int col = n0 + wn + n * 8 + 2 * t;
            float v0 = acc[m][n][0], v1 = acc[m][n][1];
            float v2 = acc[m][n][2], v3 = acc[m][n][3];
            if (RND) {
                v0 = f2tf32f(v0); v1 = f2tf32f(v1);
                v2 = f2tf32f(v2); v3 = f2tf32f(v3);
            }
            *(float2*)(Cb + row0 * N + col)       = make_float2(v0, v1);
            *(float2*)(Cb + (row0 + 8) * N + col) = make_float2(v2, v3);
        }
    }
}

// ---------------- transpose [H, RKV, HDIM] -> [H, HDIM, RKV], tf32-round on store ----------------
__global__ __launch_bounds__(256)
void transpose_up(const float* __restrict__ in, float* __restrict__ out)
{
    __shared__ float t[32][33];
    const int h = blockIdx.z;
    const int r0 = blockIdx.y * 32;   // RKV dim
    const int c0 = blockIdx.x * 32;   // HDIM dim
    const int tx = threadIdx.x & 31, ty0 = threadIdx.x >> 5;
    const float* ip = in + (long)h * RKV * HDIM;
    float* op = out + (long)h * RKV * HDIM;
    #pragma unroll
    for (int r = 0; r < 4; r++) {
        int ty = ty0 + r * 8;
        t[ty][tx] = ip[(long)(r0 + ty) * HDIM + c0 + tx];
    }
    __syncthreads();
    #pragma unroll
    for (int r = 0; r < 4; r++) {
        int ty = ty0 + r * 8;
        op[(long)(c0 + ty) * RKV + r0 + tx] = f2tf32f(t[tx][ty]);
    }
}

// ---------------- tensor-core flash attention (tf32 mma, ALiBi + causal) ----------------
// R12 version (scalar-LDS fragments; flash-LDSM regressed in R13 and was reverted).
// BM=64 q-rows/CTA, BN=64 kv per iter, d=128. 256 threads, 8 warps.
// Q/K/V tf32-rounded by producers -> raw bits feed mma directly.
// cp.async double-buffered K/V pipeline; cross-warp row softmax via smem Red/Sum.
// Output rounded to tf32 on store (consumed by the Wo GEMM's raw fragment path).
#define FQS 132
#define FVS 136
#define FPS 68
#define F_KOFF   (64*FQS)
#define F_VOFF   (F_KOFF + 2*64*FQS)
#define F_POFF   (F_VOFF + 2*64*FVS)
#define F_ROFF   (F_POFF + 64*FPS)
#define FLASH_SMEM_WORDS (F_ROFF + 256)
#define FLASH_SMEM_BYTES (FLASH_SMEM_WORDS * 4)     // 189440 B

__global__ __launch_bounds__(256)
void flash_tc(const float* __restrict__ Q, const float* __restrict__ Kg,
              const float* __restrict__ Vg, float* __restrict__ O)
{
    extern __shared__ uint32_t sm[];
    const uint32_t sbase = smem_u32(sm);
    uint32_t* Qs = sm;                              // [64][132]
    uint32_t* Ps = sm + F_POFF;                     // [64][68] tf32
    float*    Red = (float*)(sm + F_ROFF);          // [2][64] partial max
    float*    Sum = Red + 128;                      // [2][64] partial sum

    const int bh = blockIdx.y;
    const int b  = bh >> 4, h = bh & 15;
    const int qt = blockIdx.x;
    const int q0 = qt * 64;
    const int tid = threadIdx.x;
    const int wid = tid >> 5, lane = tid & 31;
    const int g = lane >> 2, t = lane & 3;
    const int mw = wid & 3;                   // M strip (16 rows)
    const int nw = wid >> 2;                  // N strip

    const float slope = exp2f(-0.5f * (float)(h + 1));
    const float scale = 0.08838834764831843f;

    const float* Qbase = Q  + ((long)(b*SEQ + q0)) * DMODEL + h*HDIM;
    const float* Kbase = Kg + ((long)(b*NHEAD + h)) * SEQ * HDIM;
    const float* Vbase = Vg + ((long)(b*NHEAD + h)) * SEQ * HDIM;

    auto issueK = [&](int k0, int buf) {
        const uint32_t base = sbase + (uint32_t)(F_KOFF + buf * 64 * FQS) * 4u;
        #pragma unroll
        for (int p = 0; p < 8; p++) {
            int idx = tid + p*256;
            int row = idx >> 5, c4 = (idx & 31) << 2;
            cp16(base + (uint32_t)(row*FQS + c4)*4u, Kbase + (long)(k0+row)*HDIM + c4);
        }
    };
    auto issueV = [&](int k0, int buf) {
        const uint32_t base = sbase + (uint32_t)(F_VOFF + buf * 64 * FVS) * 4u;
        #pragma unroll
        for (int p = 0; p < 8; p++) {
            int idx = tid + p*256;
            int row = idx >> 5, c4 = (idx & 31) << 2;
            cp16(base + (uint32_t)(row*FVS + c4)*4u, Vbase + (long)(k0+row)*HDIM + c4);
        }
    };

    // prefetch group 0: Q tile + K0 + V0
    #pragma unroll
    for (int p = 0; p < 8; p++) {
        int idx = tid + p*256;
        int row = idx >> 5, c4 = (idx & 31) << 2;
        cp16(sbase + (uint32_t)(row*FQS + c4)*4u, Qbase + (long)row*DMODEL + c4);
    }
    issueK(0, 0); issueV(0, 0);
    CP_COMMIT();

    const int r0 = mw*16 + g, r1 = r0 + 8;    // this thread's q rows (local)
    const int qi0 = q0 + r0, qi1 = q0 + r1;

    float o[8][4];
    #pragma unroll
    for (int n = 0; n < 8; n++)
        #pragma unroll
        for (int r = 0; r < 4; r++) o[n][r] = 0.f;
    float m0 = -INFINITY, m1 = -INFINITY, l0 = 0.f, l1 = 0.f;

    for (int kt = 0; kt <= qt; kt++) {
        const int k0 = kt * 64;
        __syncthreads();   // (a) all warps done with prev iteration -> buf (kt+1)&1 free
        if (kt < qt) {
            issueK(k0 + 64, (kt + 1) & 1);
            issueV(k0 + 64, (kt + 1) & 1);
            CP_COMMIT();
            CP_WAIT_1();   // K(kt),V(kt) (+Q at kt=0) complete
        } else {
            CP_WAIT_0();
        }
        __syncthreads();   // (c) visibility of completed copies to all warps

        const uint32_t* Kb = sm + F_KOFF + (size_t)(kt & 1) * (64 * FQS);
        const uint32_t* Vb = sm + F_VOFF + (size_t)(kt & 1) * (64 * FVS);

        // S = Q @ K^T  (warp tile 16x32: 4 n-subtiles), raw tf32-valued bits
        float s[4][4];
        #pragma unroll
        for (int n = 0; n < 4; n++)
            #pragma unroll
            for (int r = 0; r < 4; r++) s[n][r] = 0.f;
        #pragma unroll
        for (int ks = 0; ks < 16; ks++) {
            const int kk = ks * 8;
            uint32_t a0 = Qs[r0*FQS + kk + t];
            uint32_t a1 = Qs[r1*FQS + kk + t];
            uint32_t a2 = Qs[r0*FQS + kk + t + 4];
            uint32_t a3 = Qs[r1*FQS + kk + t + 4];
            #pragma unroll
            for (int n = 0; n < 4; n++) {
                const int nr = nw*32 + n*8 + g;
                uint32_t b0 = Kb[nr*FQS + kk + t];
                uint32_t b1 = Kb[nr*FQS + kk + t + 4];
                mma_tf32(s[n][0], s[n][1], s[n][2], s[n][3], a0, a1, a2, a3, b0, b1);
            }
        }

        // scale + ALiBi + causal, partial (this warp's 32-col half) row max
        float rv0 = -INFINITY, rv1 = -INFINITY;
        #pragma unroll
        for (int n = 0; n < 4; n++) {
            const int kj = k0 + nw*32 + n*8 + 2*t;
            s[n][0] = (kj   <= qi0) ? fmaf(s[n][0], scale, -slope*(float)(qi0-kj))   : -INFINITY;
            s[n][1] = (kj+1 <= qi0) ? fmaf(s[n][1], scale, -slope*(float)(qi0-kj-1)) : -INFINITY;
            s[n][2] = (kj   <= qi1) ? fmaf(s[n][2], scale, -slope*(float)(qi1-kj))   : -INFINITY;
            s[n][3] = (kj+1 <= qi1) ? fmaf(s[n][3], scale, -slope*(float)(qi1-kj-1)) : -INFINITY;
            rv0 = fmaxf(rv0, fmaxf(s[n][0], s[n][1]));
            rv1 = fmaxf(rv1, fmaxf(s[n][2], s[n][3]));
        }
        rv0 = fmaxf(rv0, __shfl_xor_sync(0xffffffffu, rv0, 1));
        rv0 = fmaxf(rv0, __shfl_xor_sync(0xffffffffu, rv0, 2));
        rv1 = fmaxf(rv1, __shfl_xor_sync(0xffffffffu, rv1, 1));
        rv1 = fmaxf(rv1, __shfl_xor_sync(0xffffffffu, rv1, 2));
        if (t == 0) { Red[nw*64 + r0] = rv0; Red[nw*64 + r1] = rv1; }
        __syncthreads();   // (e) partial maxes visible

        // combined (full-row) max -> consistent softmax across both warp halves
        rv0 = fmaxf(Red[r0], Red[64 + r0]);
        rv1 = fmaxf(Red[r1], Red[64 + r1]);
        const float m0n = fmaxf(m0, rv0), m1n = fmaxf(m1, rv1);
        const float al0 = __expf(m0 - m0n), al1 = __expf(m1 - m1n);
        m0 = m0n; m1 = m1n;
        float rs0 = 0.f, rs1 = 0.f;
        #pragma unroll
        for (int n = 0; n < 4; n++) {
            float p00 = __expf(s[n][0] - m0n), p01 = __expf(s[n][1] - m0n);
            float p10 = __expf(s[n][2] - m1n), p11 = __expf(s[n][3] - m1n);
            rs0 += p00 + p01; rs1 += p10 + p11;
            const int cn = nw*32 + n*8 + 2*t;
            Ps[r0*FPS + cn] = f2tf32(p00); Ps[r0*FPS + cn + 1] = f2tf32(p01);
            Ps[r1*FPS + cn] = f2tf32(p10); Ps[r1*FPS + cn + 1] = f2tf32(p11);
        }
        rs0 += __shfl_xor_sync(0xffffffffu, rs0, 1);
        rs0 += __shfl_xor_sync(0xffffffffu, rs0, 2);
        rs1 += __shfl_xor_sync(0xffffffffu, rs1, 1);
        rs1 += __shfl_xor_sync(0xffffffffu, rs1, 2);
        if (t == 0) { Sum[nw*64 + r0] = rs0; Sum[nw*64 + r1] = rs1; }
        __syncthreads();   // (g) Ps + partial sums complete

        // combined row sum; update l and rescale o
        rs0 = Sum[r0] + Sum[64 + r0];
        rs1 = Sum[r1] + Sum[64 + r1];
        l0 = l0 * al0 + rs0; l1 = l1 * al1 + rs1;
        #pragma unroll
        for (int n = 0; n < 8; n++) {
            o[n][0] *= al0; o[n][1] *= al0; o[n][2] *= al1; o[n][3] *= al1;
        }

        // O += P @ V  (warp tile 16x64: 8 d-subtiles), raw V bits
        #pragma unroll
        for (int ks = 0; ks < 8; ks++) {
            const int kk = ks * 8;
            uint32_t a0 = Ps[r0*FPS + kk + t];
            uint32_t a1 = Ps[r1*FPS + kk + t];
            uint32_t a2 = Ps[r0*FPS + kk + t + 4];
            uint32_t a3 = Ps[r1*FPS + kk + t + 4];
            #pragma unroll
            for (int n = 0; n < 8; n++) {
                const int col = nw*64 + n*8 + g;
                uint32_t b0 = Vb[(kk + t)*FVS + col];
                uint32_t b1 = Vb[(kk + t + 4)*FVS + col];
                mma_tf32(o[n][0], o[n][1], o[n][2], o[n][3], a0, a1, a2, a3, b0, b1);
            }
        }
    }

    // normalize + tf32-round + write O[b, q, h*128 + col]
    const float inv0 = 1.f / l0, inv1 = 1.f / l1;
    const long row0 = (long)(b*SEQ + q0 + r0);
    const long row1 = (long)(b*SEQ + q0 + r1);
    #pragma unroll
    for (int n = 0; n < 8; n++) {
        const int col = h*HDIM + nw*64 + n*8 + 2*t;
        *(float2*)(O + row0*DMODEL + col) = make_float2(f2tf32f(o[n][0]*inv0), f2tf32f(o[n][1]*inv0));
        *(float2*)(O + row1*DMODEL + col) = make_float2(f2tf32f(o[n][2]*inv1), f2tf32f(o[n][3]*inv1));
    }
}

// ---------------- launch ----------------
extern "C" void kernel_launch(void* const* d_in, const int* in_sizes, int n_in,
                              void* d_out, int out_size)
{
    const float* X        = (const float*)d_in[0];
    const float* Wq_down  = (const float*)d_in[1];   // [1536, 2048]
    const float* Wq_up    = (const float*)d_in[2];   // [2048, 1536]
    const float* Wkv_down = (const float*)d_in[3];   // [512, 2048]
    const float* k_up     = (const float*)d_in[4];   // [16, 512, 128]
    const float* v_up     = (const float*)d_in[5];   // [16, 512, 128]
    const float* Wo       = (const float*)d_in[6];   // [2048, 2048]
    float* out = (float*)d_out;

    float *xq, *q, *c, *kb, *vb, *ob, *kuT, *vuT;
    float *xr, *wqdr, *wqur, *wkdr, *wor;
    cudaGetSymbolAddress((void**)&xq,  g_xq);
    cudaGetSymbolAddress((void**)&q,   g_q);
    cudaGetSymbolAddress((void**)&c,   g_c);
    cudaGetSymbolAddress((void**)&kb,  g_k);
    cudaGetSymbolAddress((void**)&vb,  g_v);
    cudaGetSymbolAddress((void**)&ob,  g_o);
    cudaGetSymbolAddress((void**)&kuT, g_kuT);
    cudaGetSymbolAddress((void**)&vuT, g_vuT);
    cudaGetSymbolAddress((void**)&xr,   g_xr);
    cudaGetSymbolAddress((void**)&wqdr, g_wqdr);
    cudaGetSymbolAddress((void**)&wqur, g_wqur);
    cudaGetSymbolAddress((void**)&wkdr, g_wkdr);
    cudaGetSymbolAddress((void**)&wor,  g_wor);

    cudaFuncSetAttribute(gemm_tc<false>,
                         cudaFuncAttributeMaxDynamicSharedMemorySize, GEMM_SMEM_BYTES);
    cudaFuncSetAttribute(gemm_tc<true>,
                         cudaFuncAttributeMaxDynamicSharedMemorySize, GEMM_SMEM_BYTES);
    cudaFuncSetAttribute(gemm_tc<false>,
                         cudaFuncAttributePreferredSharedMemoryCarveout, 100);
    cudaFuncSetAttribute(gemm_tc<true>,
                         cudaFuncAttributePreferredSharedMemoryCarveout, 100);
    cudaFuncSetAttribute(flash_tc,
                         cudaFuncAttributeMaxDynamicSharedMemorySize, FLASH_SMEM_BYTES);

    dim3 blk(256);
    dim3 blkG(128);
    const int ZBIG = 1 << 30;

    // 0) tf32-round all raw GEMM inputs (one-time copies)
    round_tf32<<<512, blk>>>(X,        xr,   (long)MTOT*DMODEL/4);
    round_tf32<<<512, blk>>>(Wq_down,  wqdr, (long)RQ*DMODEL/4);
    round_tf32<<<512, blk>>>(Wq_up,    wqur, (long)DMODEL*RQ/4);
    round_tf32<<<512, blk>>>(Wkv_down, wkdr, (long)RKV*DMODEL/4);
    round_tf32<<<512, blk>>>(Wo,       wor,  (long)DMODEL*DMODEL/4);
    transpose_up<<<dim3(HDIM/32, RKV/32, NHEAD), blk>>>(k_up, kuT);
    transpose_up<<<dim3(HDIM/32, RKV/32, NHEAD), blk>>>(v_up, vuT);

    // 1) Xq = X @ Wq_down^T : [4096,1536]  (rounded: feeds GEMM 2)
    gemm_tc<true><<<dim3(RQ/128, MTOT/128, 1), blkG, GEMM_SMEM_BYTES>>>(
        xr, wqdr, xq, wqdr, xq, ZBIG, MTOT, RQ, DMODEL, 0, 0, 0, 1);
    // 2) Q = Xq @ Wq_up^T : [4096,2048]  (rounded: feeds flash)
    gemm_tc<true><<<dim3(DMODEL/128, MTOT/128, 1), blkG, GEMM_SMEM_BYTES>>>(
        xq, wqur, q, wqur, q, ZBIG, MTOT, DMODEL, RQ, 0, 0, 0, 1);
    // 3) C = X @ Wkv_down^T : [4096,512]  (rounded: feeds merged K/V GEMM)
    gemm_tc<true><<<dim3(RKV/128, MTOT/128, 1), blkG, GEMM_SMEM_BYTES>>>(
        xr, wkdr, c, wkdr, c, ZBIG, MTOT, RKV, DMODEL, 0, 0, 0, 1);
    // 4+5) merged K and V up-projections: z<32 -> K (kuT,kb), z>=32 -> V (vuT,vb)
    gemm_tc<true><<<dim3(1, SEQ/128, 2*BATCH*NHEAD), blkG, GEMM_SMEM_BYTES>>>(
        c, kuT, kb, vuT, vb, BATCH*NHEAD, SEQ, HDIM, RKV,
        (long)SEQ*RKV, (long)HDIM*RKV, (long)SEQ*HDIM, NHEAD);
    // 6) tensor-core causal+ALiBi flash attention -> ob (rounded on store)
    flash_tc<<<dim3(SEQ/64, BATCH*NHEAD), blk, FLASH_SMEM_BYTES>>>(q, kb, vb, ob);
    // 7) out = ob @ Wo^T : [4096,2048]  (NOT rounded: final output)
    gemm_tc<false><<<dim3(DMODEL/128, MTOT/128, 1), blkG, GEMM_SMEM_BYTES>>>(
        ob, wor, out, wor, out, ZBIG, MTOT, DMODEL, DMODEL, 0, 0, 0, 1);
}

// round 15
// speedup vs baseline: 1.5970x; 1.0287x over previous
#include <cuda_runtime.h>
#include <cstdint>
#include <math.h>

// ---------------- problem constants ----------------
#define BATCH 2
#define SEQ   2048
#define DMODEL 2048
#define NHEAD 16
#define HDIM  128
#define RQ    1536
#define RKV   512
#define MTOT  (BATCH*SEQ)          // 4096

// ---------------- scratch (allocation-free: __device__ globals) ----------------
__device__ float g_xq[(size_t)MTOT * RQ];            // X @ Wq_down^T (tf32-rounded)
__device__ float g_q [(size_t)MTOT * DMODEL];        // Q (tf32-rounded)
__device__ float g_c [(size_t)MTOT * RKV];           // latent C (tf32-rounded)
__device__ float g_k [(size_t)BATCH*NHEAD*SEQ*HDIM]; // K (tf32-rounded)
__device__ float g_v [(size_t)BATCH*NHEAD*SEQ*HDIM]; // V (tf32-rounded)
__device__ float g_o [(size_t)MTOT * DMODEL];        // attn out (tf32-rounded)
__device__ float g_kuT[(size_t)NHEAD*HDIM*RKV];      // k_up^T (tf32-rounded)
__device__ float g_vuT[(size_t)NHEAD*HDIM*RKV];      // v_up^T (tf32-rounded)
// tf32-rounded copies of raw inputs
__device__ float g_xr  [(size_t)MTOT * DMODEL];
__device__ float g_wqdr[(size_t)RQ * DMODEL];
__device__ float g_wqur[(size_t)DMODEL * RQ];
__device__ float g_wkdr[(size_t)RKV * DMODEL];
__device__ float g_wor [(size_t)DMODEL * DMODEL];

// ---------------- helpers ----------------
__device__ __forceinline__ uint32_t smem_u32(const void* p) {
    uint32_t a;
    asm("{ .reg .u64 t; cvta.to.shared.u64 t, %1; cvt.u32.u64 %0, t; }" : "=r"(a) : "l"(p));
    return a;
}
__device__ __forceinline__ uint32_t f2tf32(float x) {
    uint32_t r;
    asm("cvt.rna.tf32.f32 %0, %1;" : "=r"(r) : "f"(x));
    return r;
}
__device__ __forceinline__ float f2tf32f(float x) { return __uint_as_float(f2tf32(x)); }
__device__ __forceinline__ void cp16(uint32_t saddr, const void* gaddr) {
    asm volatile("cp.async.cg.shared.global [%0], [%1], 16;" :: "r"(saddr), "l"(gaddr));
}
#define CP_COMMIT()  asm volatile("cp.async.commit_group;" ::: "memory")
#define CP_WAIT_1()  asm volatile("cp.async.wait_group 1;" ::: "memory")
#define CP_WAIT_0()  asm volatile("cp.async.wait_group 0;" ::: "memory")

// ldmatrix x4: four 8x(16B) matrices; for tf32 fragments lane L <- (row L/4, word L%4).
__device__ __forceinline__ void ldsm4(uint32_t& r0, uint32_t& r1, uint32_t& r2, uint32_t& r3,
                                      uint32_t saddr) {
    asm volatile("ldmatrix.sync.aligned.m8n8.x4.shared.b16 {%0,%1,%2,%3}, [%4];"
                 : "=r"(r0), "=r"(r1), "=r"(r2), "=r"(r3) : "r"(saddr));
}

// mma.sync m16n8k8 tf32: D = A(16x8 row) * B(8x8 col) + C, fp32 accum.
__device__ __forceinline__ void mma_tf32(float& c0, float& c1, float& c2, float& c3,
                                         uint32_t a0, uint32_t a1, uint32_t a2, uint32_t a3,
                                         uint32_t b0, uint32_t b1) {
    asm volatile(
        "mma.sync.aligned.m16n8k8.row.col.f32.tf32.tf32.f32 "
        "{%0,%1,%2,%3}, {%4,%5,%6,%7}, {%8,%9}, {%0,%1,%2,%3};"
        : "+f"(c0), "+f"(c1), "+f"(c2), "+f"(c3)
        : "r"(a0), "r"(a1), "r"(a2), "r"(a3), "r"(b0), "r"(b1));
}

// ---------------- elementwise tf32 rounding copy ----------------
__global__ __launch_bounds__(256)
void round_tf32(const float* __restrict__ in, float* __restrict__ out, long n4)
{
    long i = (long)blockIdx.x * blockDim.x + threadIdx.x;
    long stride = (long)gridDim.x * blockDim.x;
    for (; i < n4; i += stride) {
        float4 v = ((const float4*)in)[i];
        v.x = f2tf32f(v.x); v.y = f2tf32f(v.y); v.z = f2tf32f(v.z); v.w = f2tf32f(v.w);
        ((float4*)out)[i] = v;
    }
}

// ---------------- tf32 tensor-core GEMM: C = A @ B^T (cp.async + ldmatrix) ----------------
// ALL inputs must be tf32-valued fp32 in gmem (pre-rounded) -> no cvt anywhere.
// A [M,K] row-major, B [N,K] row-major. M%128==0, N%128==0, K%32==0.
// CTA 128x128, BK=32, 128 threads = 4 warps, warp tile 64x64 (4x8 of m16n8k8).
// Fragments via ldmatrix.x4: per k8-step 8 LDSM + 32 MMA.
// Dual-output batching: z >= nz1 switches to (B2, C2) with z -= nz1 (merged K/V GEMMs).
// RND: round outputs to tf32 (for tensors consumed by later mma stages).
#define BK 32
#define ST 36                       // row stride in words (32 + 4 pad): LDSM phases conflict-free
#define GEMM_BUF_WORDS (128 * ST)   // 4608 words per tile buffer
#define GEMM_SMEM_BYTES (4 * GEMM_BUF_WORDS * 4)   // A0,B0,A1,B1 = 73728 B

template<bool RND>
__global__ __launch_bounds__(128, 2)
void gemm_tc(const float* __restrict__ A, const float* __restrict__ B,
             float* __restrict__ C,
             const float* __restrict__ B2, float* __restrict__ C2, int nz1,
             int M, int N, int K,
             long sA, long sB, long sC, int hmod)
{
    extern __shared__ uint32_t sh[];
    const uint32_t sbase = smem_u32(sh);

    const int tid = threadIdx.x;
    const int wid = tid >> 5, lane = tid & 31;
    const int g = lane >> 2, t = lane & 3;           // groupID / threadID_in_group
    const int quad = lane >> 3, rin = lane & 7;      // ldmatrix lane mapping
    int z = blockIdx.z;
    const float* Bp = B;
    float* Cp = C;
    if (z >= nz1) { Bp = B2; Cp = C2; z -= nz1; }
    const float* Ab = A + (long)(z / hmod) * sA;
    const float* Bb = Bp + (long)(z % hmod) * sB;
    float* Cb = Cp + (long)z * sC;
    const int m0 = blockIdx.y * 128;
    const int n0 = blockIdx.x * 128;

    const int wm = (wid & 1) * 64;                   // warp tile origin in M
    const int wn = (wid >> 1) * 64;                  // warp tile origin in N

    // per-thread ldmatrix base offsets (words)
    const uint32_t aoff_t = (uint32_t)((wm + (quad & 1) * 8 + rin) * ST + (quad >> 1) * 4);
    const uint32_t boff_t = (uint32_t)((wn + (quad >> 1) * 8 + rin) * ST + (quad & 1) * 4);

    float acc[4][8][4];
    #pragma unroll
    for (int m = 0; m < 4; m++)
        #pragma unroll
        for (int n = 0; n < 8; n++)
            #pragma unroll
            for (int r = 0; r < 4; r++) acc[m][n][r] = 0.f;

    const int lrow = tid >> 3;          // 0..15
    const int lc4  = (tid & 7) << 2;    // 0,4,..,28

    auto issue = [&](int k0, int b) {
        const uint32_t abase = sbase + (uint32_t)b * (2u * GEMM_BUF_WORDS * 4u);
        const uint32_t bbase = abase + GEMM_BUF_WORDS * 4u;
        #pragma unroll
        for (int p = 0; p < 8; p++) {
            const int row = lrow + p * 16;
            const uint32_t so = (uint32_t)(row * ST + lc4) * 4u;
            cp16(abase + so, Ab + (long)(m0 + row) * K + k0 + lc4);
            cp16(bbase + so, Bb + (long)(n0 + row) * K + k0 + lc4);
        }
        CP_COMMIT();
    };

    const int KT = K >> 5;
    issue(0, 0);

    for (int kt = 0; kt < KT; kt++) {
        if (kt + 1 < KT) { issue((kt + 1) << 5, (kt + 1) & 1); CP_WAIT_1(); }
        else             { CP_WAIT_0(); }
        __syncthreads();

        const uint32_t abuf = sbase + (uint32_t)(kt & 1) * (2u * GEMM_BUF_WORDS * 4u);
        const uint32_t bbuf = abuf + GEMM_BUF_WORDS * 4u;
        const uint32_t aaddr = abuf + aoff_t * 4u;
        const uint32_t baddr = bbuf + boff_t * 4u;

        #pragma unroll
        for (int ks = 0; ks < BK / 8; ks++) {
            const uint32_t kk = (uint32_t)(ks * 8);
            uint32_t af[4][4], bf[8][2];
            #pragma unroll
            for (int m = 0; m < 4; m++)
                ldsm4(af[m][0], af[m][1], af[m][2], af[m][3],
                      aaddr + (uint32_t)(m * 16 * ST + kk) * 4u);
            #pragma unroll
            for (int np = 0; np < 4; np++)
                ldsm4(bf[2*np][0], bf[2*np][1], bf[2*np+1][0], bf[2*np+1][1],
                      baddr + (uint32_t)(np * 16 * ST + kk) * 4u);
            #pragma unroll
            for (int m = 0; m < 4; m++)
                #pragma unroll
                for (int n = 0; n < 8; n++)
                    mma_tf32(acc[m][n][0], acc[m][n][1], acc[m][n][2], acc[m][n][3],
                             af[m][0], af[m][1], af[m][2], af[m][3],
                             bf[n][0], bf[n][1]);
        }
        __syncthreads();
    }

    #pragma unroll
    for (int m = 0; m < 4; m++) {
        const long row0 = m0 + wm + m * 16 + g;
        #pragma unroll
        for (int n = 0; n < 8; n++) {
            const int col = n0 + wn + n * 8 + 2 * t;
            float v0 = acc[m][n][0], v1 = acc[m][n][1];
            float v2 = acc[m][n][2], v3 = acc[m][n][3];
            if (RND) {
                v0 = f2tf32f(v0); v1 = f2tf32f(v1);
                v2 = f2tf32f(v2); v3 = f2tf32f(v3);
            }
            *(float2*)(Cb + row0 * N + col)       = make_float2(v0, v1);
            *(float2*)(Cb + (row0 + 8) * N + col) = make_float2(v2, v3);
        }
    }
}

// ---------------- transpose [H, RKV, HDIM] -> [H, HDIM, RKV], tf32-round on store ----------------
__global__ __launch_bounds__(256)
void transpose_up(const float* __restrict__ in, float* __restrict__ out)
{
    __shared__ float t[32][33];
    const int h = blockIdx.z;
    const int r0 = blockIdx.y * 32;   // RKV dim
    const int c0 = blockIdx.x * 32;   // HDIM dim
    const int tx = threadIdx.x & 31, ty0 = threadIdx.x >> 5;
    const float* ip = in + (long)h * RKV * HDIM;
    float* op = out + (long)h * RKV * HDIM;
    #pragma unroll
    for (int r = 0; r < 4; r++) {
        int ty = ty0 + r * 8;
        t[ty][tx] = ip[(long)(r0 + ty) * HDIM + c0 + tx];
    }
    __syncthreads();
    #pragma unroll
    for (int r = 0; r < 4; r++) {
        int ty = ty0 + r * 8;
        op[(long)(c0 + ty) * RKV + r0 + tx] = f2tf32f(t[tx][ty]);
    }
}

// ---------------- tensor-core flash attention v2 (tf32 mma, ALiBi + causal) ----------------
// BM=128 q-rows/CTA, BN=64 kv per iter, d=128. 256 threads, 8 warps.
// Each warp owns 16 q-rows x FULL 64 kv-cols -> softmax is warp-local (quad shuffles only,
// no cross-warp Red/Sum, no extra block barriers). P written+read by the SAME warp
// (one __syncwarp). K double-buffered (prefetch next tile); V single-buffered, issued at
// iteration start and completed during the S phase. 2 __syncthreads per KV tile.
#define FQS 132
#define FVS 136
#define FPS 68
#define F2_KOFF  (128*FQS)                    // 16896
#define F2_VOFF  (F2_KOFF + 2*64*FQS)         // 33792
#define F2_POFF  (F2_VOFF + 64*FVS)           // 42496
#define FLASH_SMEM_WORDS (F2_POFF + 128*FPS)  // 51200
#define FLASH_SMEM_BYTES (FLASH_SMEM_WORDS * 4)  // 204800 B

__global__ __launch_bounds__(256)
void flash_tc(const float* __restrict__ Q, const float* __restrict__ Kg,
              const float* __restrict__ Vg, float* __restrict__ O)
{
    extern __shared__ uint32_t sm[];
    const uint32_t sbase = smem_u32(sm);
    uint32_t* Qs = sm;                              // [128][132]
    uint32_t* Ps = sm + F2_POFF;                    // [128][68] tf32

    const int bh = blockIdx.y;
    const int b  = bh >> 4, h = bh & 15;
    const int qt = blockIdx.x;
    const int q0 = qt * 128;
    const int tid = threadIdx.x;
    const int wid = tid >> 5, lane = tid & 31;
    const int g = lane >> 2, t = lane & 3;

    const float slope = exp2f(-0.5f * (float)(h + 1));
    const float scale = 0.08838834764831843f;

    const float* Qbase = Q  + ((long)(b*SEQ + q0)) * DMODEL + h*HDIM;
    const float* Kbase = Kg + ((long)(b*NHEAD + h)) * SEQ * HDIM;
    const float* Vbase = Vg + ((long)(b*NHEAD + h)) * SEQ * HDIM;

    auto issueK = [&](int k0, int buf) {
        const uint32_t base = sbase + (uint32_t)(F2_KOFF + buf * 64 * FQS) * 4u;
        #pragma unroll
        for (int p = 0; p < 8; p++) {
            int idx = tid + p*256;
            int row = idx >> 5, c4 = (idx & 31) << 2;
            cp16(base + (uint32_t)(row*FQS + c4)*4u, Kbase + (long)(k0+row)*HDIM + c4);
        }
        CP_COMMIT();
    };
    auto issueV = [&](int k0) {
        const uint32_t base = sbase + (uint32_t)F2_VOFF * 4u;
        #pragma unroll
        for (int p = 0; p < 8; p++) {
            int idx = tid + p*256;
            int row = idx >> 5, c4 = (idx & 31) << 2;
            cp16(base + (uint32_t)(row*FVS + c4)*4u, Vbase + (long)(k0+row)*HDIM + c4);
        }
        CP_COMMIT();
    };

    // prologue group: Q tile (128x128) + K0
    #pragma unroll
    for (int p = 0; p < 16; p++) {
        int idx = tid + p*256;
        int row = idx >> 5, c4 = (idx & 31) << 2;
        cp16(sbase + (uint32_t)(row*FQS + c4)*4u, Qbase + (long)row*DMODEL + c4);
    }
    {   // K0 into buf 0 (same commit group as Q)
        const uint32_t base = sbase + (uint32_t)F2_KOFF * 4u;
        #pragma unroll
        for (int p = 0; p < 8; p++) {
            int idx = tid + p*256;
            int row = idx >> 5, c4 = (idx & 31) << 2;
            cp16(base + (uint32_t)(row*FQS + c4)*4u, Kbase + (long)row*HDIM + c4);
        }
        CP_COMMIT();
    }

    const int r0 = wid*16 + g, r1 = r0 + 8;   // this thread's q rows (local, warp-owned strip)
    const int qi0 = q0 + r0, qi1 = q0 + r1;

    float o[16][4];
    #pragma unroll
    for (int n = 0; n < 16; n++)
        #pragma unroll
        for (int r = 0; r < 4; r++) o[n][r] = 0.f;
    float m0 = -INFINITY, m1 = -INFINITY, l0 = 0.f, l1 = 0.f;

    const int ktmax = 2*qt + 1;
    for (int kt = 0; kt <= ktmax; kt++) {
        const int k0 = kt * 64;
        __syncthreads();   // (a) prev iter's K-buf/V reads complete
        issueV(k0);        // V(kt): completes during S phase
        if (kt < ktmax) { issueK(k0 + 64, (kt + 1) & 1); CP_WAIT_1(); }
        else            { CP_WAIT_0(); }
        // wait_group 1 leaves only the newest group (K(kt+1)) in flight:
        // Q (kt=0), K(kt), V(kt) are complete here.
        __syncthreads();   // (c) visibility of completed copies

        const uint32_t* Kb = sm + F2_KOFF + (size_t)(kt & 1) * (64 * FQS);
        const uint32_t* Vb = sm + F2_VOFF;

        // S = Q @ K^T  (warp tile 16x64: 8 n-subtiles)
        float s[8][4];
        #pragma unroll
        for (int n = 0; n < 8; n++)
            #pragma unroll
            for (int r = 0; r < 4; r++) s[n][r] = 0.f;
        #pragma unroll
        for (int ks = 0; ks < 16; ks++) {
            const int kk = ks * 8;
            uint32_t a0 = Qs[r0*FQS + kk + t];
            uint32_t a1 = Qs[r1*FQS + kk + t];
            uint32_t a2 = Qs[r0*FQS + kk + t + 4];
            uint32_t a3 = Qs[r1*FQS + kk + t + 4];
            #pragma unroll
            for (int n = 0; n < 8; n++) {
                const int nr = n*8 + g;
                uint32_t b0 = Kb[nr*FQS + kk + t];
                uint32_t b1 = Kb[nr*FQS + kk + t + 4];
                mma_tf32(s[n][0], s[n][1], s[n][2], s[n][3], a0, a1, a2, a3, b0, b1);
            }
        }

        // scale + ALiBi + causal; warp-local row max over the full 64 cols
        float rv0 = -INFINITY, rv1 = -INFINITY;
        #pragma unroll
        for (int n = 0; n < 8; n++) {
            const int kj = k0 + n*8 + 2*t;
            s[n][0] = (kj   <= qi0) ? fmaf(s[n][0], scale, -slope*(float)(qi0-kj))   : -INFINITY;
            s[n][1] = (kj+1 <= qi0) ? fmaf(s[n][1], scale, -slope*(float)(qi0-kj-1)) : -INFINITY;
            s[n][2] = (kj   <= qi1) ? fmaf(s[n][2], scale, -slope*(float)(qi1-kj))   : -INFINITY;
            s[n][3] = (kj+1 <= qi1) ? fmaf(s[n][3], scale, -slope*(float)(qi1-kj-1)) : -INFINITY;
            rv0 = fmaxf(rv0, fmaxf(s[n][0], s[n][1]));
            rv1 = fmaxf(rv1, fmaxf(s[n][2], s[n][3]));
        }
        rv0 = fmaxf(rv0, __shfl_xor_sync(0xffffffffu, rv0, 1));
        rv0 = fmaxf(rv0, __shfl_xor_sync(0xffffffffu, rv0, 2));
        rv1 = fmaxf(rv1, __shfl_xor_sync(0xffffffffu, rv1, 1));
        rv1 = fmaxf(rv1, __shfl_xor_sync(0xffffffffu, rv1, 2));
        const float m0n = fmaxf(m0, rv0), m1n = fmaxf(m1, rv1);
        const float al0 = __expf(m0 - m0n), al1 = __expf(m1 - m1n);
        m0 = m0n; m1 = m1n;
        float rs0 = 0.f, rs1 = 0.f;
        #pragma unroll
        for (int n = 0; n < 8; n++) {
            float p00 = __expf(s[n][0] - m0n), p01 = __expf(s[n][1] - m0n);
            float p10 = __expf(s[n][2] - m1n), p11 = __expf(s[n][3] - m1n);
            rs0 += p00 + p01; rs1 += p10 + p11;
            const int cn = n*8 + 2*t;
            Ps[r0*FPS + cn] = f2tf32(p00); Ps[r0*FPS + cn + 1] = f2tf32(p01);
            Ps[r1*FPS + cn] = f2tf32(p10); Ps[r1*FPS + cn + 1] = f2tf32(p11);
        }
        rs0 += __shfl_xor_sync(0xffffffffu, rs0, 1);
        rs0 += __shfl_xor_sync(0xffffffffu, rs0, 2);
        rs1 += __shfl_xor_sync(0xffffffffu, rs1, 1);
        rs1 += __shfl_xor_sync(0xffffffffu, rs1, 2);
        l0 = l0 * al0 + rs0; l1 = l1 * al1 + rs1;
        #pragma unroll
        for (int n = 0; n < 16; n++) {
            o[n][0] *= al0; o[n][1] *= al0; o[n][2] *= al1; o[n][3] *= al1;
        }
        __syncwarp();      // P visible within the owning warp (cross-lane smem)

        // O += P @ V  (warp tile 16x128: 16 d-subtiles); P rows are warp-private
        #pragma unroll
        for (int ks = 0; ks < 8; ks++) {
            const int kk = ks * 8;
            uint32_t a0 = Ps[r0*FPS + kk + t];
            uint32_t a1 = Ps[r1*FPS + kk + t];
            uint32_t a2 = Ps[r0*FPS + kk + t + 4];
            uint32_t a3 = Ps[r1*FPS + kk + t + 4];
            #pragma unroll
            for (int n = 0; n < 16; n++) {
                const int col = n*8 + g;
                uint32_t b0 = Vb[(kk + t)*FVS + col];
                uint32_t b1 = Vb[(kk + t + 4)*FVS + col];
                mma_tf32(o[n][0], o[n][1], o[n][2], o[n][3], a0, a1, a2, a3, b0, b1);
            }
        }
    }

    // normalize + tf32-round + write O[b, q, h*128 + col]
    const float inv0 = 1.f / l0, inv1 = 1.f / l1;
    const long row0 = (long)(b*SEQ + q0 + r0);
    const long row1 = (long)(b*SEQ + q0 + r1);
    #pragma unroll
    for (int n = 0; n < 16; n++) {
        const int col = h*HDIM + n*8 + 2*t;
        *(float2*)(O + row0*DMODEL + col) = make_float2(f2tf32f(o[n][0]*inv0), f2tf32f(o[n][1]*inv0));
        *(float2*)(O + row1*DMODEL + col) = make_float2(f2tf32f(o[n][2]*inv1), f2tf32f(o[n][3]*inv1));
    }
}

// ---------------- launch ----------------
extern "C" void kernel_launch(void* const* d_in, const int* in_sizes, int n_in,
                              void* d_out, int out_size)
{
    const float* X        = (const float*)d_in[0];
    const float* Wq_down  = (const float*)d_in[1];   // [1536, 2048]
    const float* Wq_up    = (const float*)d_in[2];   // [2048, 1536]
    const float* Wkv_down = (const float*)d_in[3];   // [512, 2048]
    const float* k_up     = (const float*)d_in[4];   // [16, 512, 128]
    const float* v_up     = (const float*)d_in[5];   // [16, 512, 128]
    const float* Wo       = (const float*)d_in[6];   // [2048, 2048]
    float* out = (float*)d_out;

    float *xq, *q, *c, *kb, *vb, *ob, *kuT, *vuT;
    float *xr, *wqdr, *wqur, *wkdr, *wor;
    cudaGetSymbolAddress((void**)&xq,  g_xq);
    cudaGetSymbolAddress((void**)&q,   g_q);
    cudaGetSymbolAddress((void**)&c,   g_c);
    cudaGetSymbolAddress((void**)&kb,  g_k);
    cudaGetSymbolAddress((void**)&vb,  g_v);
    cudaGetSymbolAddress((void**)&ob,  g_o);
    cudaGetSymbolAddress((void**)&kuT, g_kuT);
    cudaGetSymbolAddress((void**)&vuT, g_vuT);
    cudaGetSymbolAddress((void**)&xr,   g_xr);
    cudaGetSymbolAddress((void**)&wqdr, g_wqdr);
    cudaGetSymbolAddress((void**)&wqur, g_wqur);
    cudaGetSymbolAddress((void**)&wkdr, g_wkdr);
    cudaGetSymbolAddress((void**)&wor,  g_wor);

    cudaFuncSetAttribute(gemm_tc<false>,
                         cudaFuncAttributeMaxDynamicSharedMemorySize, GEMM_SMEM_BYTES);
    cudaFuncSetAttribute(gemm_tc<true>,
                         cudaFuncAttributeMaxDynamicSharedMemorySize, GEMM_SMEM_BYTES);
    cudaFuncSetAttribute(gemm_tc<false>,
                         cudaFuncAttributePreferredSharedMemoryCarveout, 100);
    cudaFuncSetAttribute(gemm_tc<true>,
                         cudaFuncAttributePreferredSharedMemoryCarveout, 100);
    cudaFuncSetAttribute(flash_tc,
                         cudaFuncAttributeMaxDynamicSharedMemorySize, FLASH_SMEM_BYTES);

    dim3 blk(256);
    dim3 blkG(128);
    const int ZBIG = 1 << 30;

    // 0) tf32-round all raw GEMM inputs (one-time copies)
    round_tf32<<<512, blk>>>(X,        xr,   (long)MTOT*DMODEL/4);
    round_tf32<<<512, blk>>>(Wq_down,  wqdr, (long)RQ*DMODEL/4);
    round_tf32<<<512, blk>>>(Wq_up,    wqur, (long)DMODEL*RQ/4);
    round_tf32<<<512, blk>>>(Wkv_down, wkdr, (long)RKV*DMODEL/4);
    round_tf32<<<512, blk>>>(Wo,       wor,  (long)DMODEL*DMODEL/4);
    transpose_up<<<dim3(HDIM/32, RKV/32, NHEAD), blk>>>(k_up, kuT);
    transpose_up<<<dim3(HDIM/32, RKV/32, NHEAD), blk>>>(v_up, vuT);

    // 1) Xq = X @ Wq_down^T : [4096,1536]  (rounded: feeds GEMM 2)
    gemm_tc<true><<<dim3(RQ/128, MTOT/128, 1), blkG, GEMM_SMEM_BYTES>>>(
        xr, wqdr, xq, wqdr, xq, ZBIG, MTOT, RQ, DMODEL, 0, 0, 0, 1);
    // 2) Q = Xq @ Wq_up^T : [4096,2048]  (rounded: feeds flash)
    gemm_tc<true><<<dim3(DMODEL/128, MTOT/128, 1), blkG, GEMM_SMEM_BYTES>>>(
        xq, wqur, q, wqur, q, ZBIG, MTOT, DMODEL, RQ, 0, 0, 0, 1);
    // 3) C = X @ Wkv_down^T : [4096,512]  (rounded: feeds merged K/V GEMM)
    gemm_tc<true><<<dim3(RKV/128, MTOT/128, 1), blkG, GEMM_SMEM_BYTES>>>(
        xr, wkdr, c, wkdr, c, ZBIG, MTOT, RKV, DMODEL, 0, 0, 0, 1);
    // 4+5) merged K and V up-projections: z<32 -> K (kuT,kb), z>=32 -> V (vuT,vb)
    gemm_tc<true><<<dim3(1, SEQ/128, 2*BATCH*NHEAD), blkG, GEMM_SMEM_BYTES>>>(
        c, kuT, kb, vuT, vb, BATCH*NHEAD, SEQ, HDIM, RKV,
        (long)SEQ*RKV, (long)HDIM*RKV, (long)SEQ*HDIM, NHEAD);
    // 6) tensor-core causal+ALiBi flash attention (BM=128) -> ob (rounded on store)
    flash_tc<<<dim3(SEQ/128, BATCH*NHEAD), blk, FLASH_SMEM_BYTES>>>(q, kb, vb, ob);
    // 7) out = ob @ Wo^T : [4096,2048]  (NOT rounded: final output)
    gemm_tc<false><<<dim3(DMODEL/128, MTOT/128, 1), blkG, GEMM_SMEM_BYTES>>>(
        ob, wor, out, wor, out, ZBIG, MTOT, DMODEL, DMODEL, 0, 0, 0, 1);
}

// round 16
// speedup vs baseline: 2.2654x; 1.4185x over previous
#include <cuda_runtime.h>
#include <cuda_fp16.h>
#include <cstdint>
#include <math.h>

// ---------------- problem constants ----------------
#define BATCH 2
#define SEQ   2048
#define DMODEL 2048
#define NHEAD 16
#define HDIM  128
#define RQ    1536
#define RKV   512
#define MTOT  (BATCH*SEQ)          // 4096

// ---------------- scratch (allocation-free: __device__ globals) ----------------
__device__ __half g_xq[(size_t)MTOT * RQ];             // X @ Wq_down^T (fp16)
__device__ float  g_q [(size_t)MTOT * DMODEL];         // Q (fp32, tf32-rounded, for flash)
__device__ __half g_c [(size_t)MTOT * RKV];            // latent C (fp16)
__device__ float  g_k [(size_t)BATCH*NHEAD*SEQ*HDIM];  // K (fp32, tf32-rounded)
__device__ float  g_v [(size_t)BATCH*NHEAD*SEQ*HDIM];  // V (fp32, tf32-rounded)
__device__ __half g_o [(size_t)MTOT * DMODEL];         // attn out (fp16, feeds Wo GEMM)
__device__ __half g_kuT[(size_t)NHEAD*HDIM*RKV];       // k_up^T (fp16)
__device__ __half g_vuT[(size_t)NHEAD*HDIM*RKV];       // v_up^T (fp16)
// fp16 copies of raw inputs
__device__ __half g_xr  [(size_t)MTOT * DMODEL];
__device__ __half g_wqdr[(size_t)RQ * DMODEL];
__device__ __half g_wqur[(size_t)DMODEL * RQ];
__device__ __half g_wkdr[(size_t)RKV * DMODEL];
__device__ __half g_wor [(size_t)DMODEL * DMODEL];

// ---------------- helpers ----------------
__device__ __forceinline__ uint32_t smem_u32(const void* p) {
    uint32_t a;
    asm("{ .reg .u64 t; cvta.to.shared.u64 t, %1; cvt.u32.u64 %0, t; }" : "=r"(a) : "l"(p));
    return a;
}
__device__ __forceinline__ uint32_t f2tf32(float x) {
    uint32_t r;
    asm("cvt.rna.tf32.f32 %0, %1;" : "=r"(r) : "f"(x));
    return r;
}
__device__ __forceinline__ float f2tf32f(float x) { return __uint_as_float(f2tf32(x)); }
__device__ __forceinline__ void cp16(uint32_t saddr, const void* gaddr) {
    asm volatile("cp.async.cg.shared.global [%0], [%1], 16;" :: "r"(saddr), "l"(gaddr));
}
#define CP_COMMIT()  asm volatile("cp.async.commit_group;" ::: "memory")
#define CP_WAIT_1()  asm volatile("cp.async.wait_group 1;" ::: "memory")
#define CP_WAIT_0()  asm volatile("cp.async.wait_group 0;" ::: "memory")

// ldmatrix x4 (b16): four 8x8 16-bit matrices; lane l <- (row l>>2, elem pair 2(l&3)).
__device__ __forceinline__ void ldsm4(uint32_t& r0, uint32_t& r1, uint32_t& r2, uint32_t& r3,
                                      uint32_t saddr) {
    asm volatile("ldmatrix.sync.aligned.m8n8.x4.shared.b16 {%0,%1,%2,%3}, [%4];"
                 : "=r"(r0), "=r"(r1), "=r"(r2), "=r"(r3) : "r"(saddr));
}

// mma.sync m16n8k16 fp16: D = A(16x16 row) * B(8x16 col) + C, fp32 accum.
__device__ __forceinline__ void mma_f16(float& c0, float& c1, float& c2, float& c3,
                                        uint32_t a0, uint32_t a1, uint32_t a2, uint32_t a3,
                                        uint32_t b0, uint32_t b1) {
    asm volatile(
        "mma.sync.aligned.m16n8k16.row.col.f32.f16.f16.f32 "
        "{%0,%1,%2,%3}, {%4,%5,%6,%7}, {%8,%9}, {%0,%1,%2,%3};"
        : "+f"(c0), "+f"(c1), "+f"(c2), "+f"(c3)
        : "r"(a0), "r"(a1), "r"(a2), "r"(a3), "r"(b0), "r"(b1));
}

// mma.sync m16n8k8 tf32 (flash only)
__device__ __forceinline__ void mma_tf32(float& c0, float& c1, float& c2, float& c3,
                                         uint32_t a0, uint32_t a1, uint32_t a2, uint32_t a3,
                                         uint32_t b0, uint32_t b1) {
    asm volatile(
        "mma.sync.aligned.m16n8k8.row.col.f32.tf32.tf32.f32 "
        "{%0,%1,%2,%3}, {%4,%5,%6,%7}, {%8,%9}, {%0,%1,%2,%3};"
        : "+f"(c0), "+f"(c1), "+f"(c2), "+f"(c3)
        : "r"(a0), "r"(a1), "r"(a2), "r"(a3), "r"(b0), "r"(b1));
}

// ---------------- elementwise fp16 rounding copy ----------------
__global__ __launch_bounds__(256)
void round_half(const float* __restrict__ in, __half* __restrict__ out, long n4)
{
    long i = (long)blockIdx.x * blockDim.x + threadIdx.x;
    long stride = (long)gridDim.x * blockDim.x;
    for (; i < n4; i += stride) {
        float4 v = ((const float4*)in)[i];
        ((__half2*)out)[2*i]   = __floats2half2_rn(v.x, v.y);
        ((__half2*)out)[2*i+1] = __floats2half2_rn(v.z, v.w);
    }
}

// ---------------- fp16 tensor-core GEMM: C = A @ B^T (cp.async + ldmatrix) ----------------
// A [M,K], B [N,K] row-major __half. M%128==0, N%128==0, K%32==0.
// CTA 128x128, BK=32 halves, 128 threads = 4 warps, warp tile 64x64 (4x8 of m16n8k16).
// Per BK chunk: 16 LDSM + 64 MMA (vs 32+128 for tf32).
// OM: 0 = fp32 out, 1 = fp32 tf32-rounded out (flash inputs), 2 = fp16 out.
// Dual-output batching: z >= nz1 switches to (B2, C2) with z -= nz1 (merged K/V GEMMs).
#define BKH 32                       // halves per chunk
#define STH 40                       // row stride in halves (80 B): LDSM phases conflict-free
#define GEMM_BUF_HALVES (128 * STH)  // 5120 halves = 10240 B per tile buffer
#define GEMM_SMEM_BYTES (4 * GEMM_BUF_HALVES * 2)   // A0,B0,A1,B1 = 40960 B

template<int OM>
__global__ __launch_bounds__(128, 2)
void gemm_tc(const __half* __restrict__ A, const __half* __restrict__ B,
             void* __restrict__ C,
             const __half* __restrict__ B2, void* __restrict__ C2, int nz1,
             int M, int N, int K,
             long sA, long sB, long sC, int hmod)
{
    extern __shared__ __half sh[];
    const uint32_t sbase = smem_u32(sh);

    const int tid = threadIdx.x;
    const int wid = tid >> 5, lane = tid & 31;
    const int g = lane >> 2, t = lane & 3;
    const int quad = lane >> 3, rin = lane & 7;
    int z = blockIdx.z;
    const __half* Bp = B;
    void* Cv = C;
    if (z >= nz1) { Bp = B2; Cv = C2; z -= nz1; }
    const __half* Ab = A + (long)(z / hmod) * sA;
    const __half* Bb = Bp + (long)(z % hmod) * sB;
    const int m0 = blockIdx.y * 128;
    const int n0 = blockIdx.x * 128;

    const int wm = (wid & 1) * 64;
    const int wn = (wid >> 1) * 64;

    // per-thread ldmatrix base offsets (halves)
    // A: r0=(rows+0,k+0) r1=(rows+8,k+0) r2=(rows+0,k+8) r3=(rows+8,k+8)
    const uint32_t aoff_t = (uint32_t)((wm + (quad & 1) * 8 + rin) * STH + (quad >> 1) * 8);
    // B: r0=(n0-7,k+0) r1=(n0-7,k+8) r2=(n8-15,k+0) r3=(n8-15,k+8)
    const uint32_t boff_t = (uint32_t)((wn + (quad >> 1) * 8 + rin) * STH + (quad & 1) * 8);

    float acc[4][8][4];
    #pragma unroll
    for (int m = 0; m < 4; m++)
        #pragma unroll
        for (int n = 0; n < 8; n++)
            #pragma unroll
            for (int r = 0; r < 4; r++) acc[m][n][r] = 0.f;

    const int lrow = tid >> 2;          // 0..31
    const int lc8  = (tid & 3) * 8;     // halves: 0,8,16,24

    auto issue = [&](int k0, int b) {
        const uint32_t abase = sbase + (uint32_t)b * (2u * GEMM_BUF_HALVES * 2u);
        const uint32_t bbase = abase + GEMM_BUF_HALVES * 2u;
        #pragma unroll
        for (int p = 0; p < 4; p++) {
            const int row = lrow + p * 32;
            const uint32_t so = (uint32_t)(row * STH + lc8) * 2u;
            cp16(abase + so, Ab + (long)(m0 + row) * K + k0 + lc8);
            cp16(bbase + so, Bb + (long)(n0 + row) * K + k0 + lc8);
        }
        CP_COMMIT();
    };

    const int KT = K >> 5;
    issue(0, 0);

    for (int kt = 0; kt < KT; kt++) {
        if (kt + 1 < KT) { issue((kt + 1) << 5, (kt + 1) & 1); CP_WAIT_1(); }
        else             { CP_WAIT_0(); }
        __syncthreads();

        const uint32_t abuf = sbase + (uint32_t)(kt & 1) * (2u * GEMM_BUF_HALVES * 2u);
        const uint32_t bbuf = abuf + GEMM_BUF_HALVES * 2u;
        const uint32_t aaddr = abuf + aoff_t * 2u;
        const uint32_t baddr = bbuf + boff_t * 2u;

        #pragma unroll
        for (int ks = 0; ks < 2; ks++) {        // 2 x k16 steps per BK=32
            const uint32_t kk = (uint32_t)(ks * 16);
            uint32_t af[4][4], bf[8][2];
            #pragma unroll
            for (int m = 0; m < 4; m++)
                ldsm4(af[m][0], af[m][1], af[m][2], af[m][3],
                      aaddr + (uint32_t)(m * 16 * STH + kk) * 2u);
            #pragma unroll
            for (int np = 0; np < 4; np++)
                ldsm4(bf[2*np][0], bf[2*np][1], bf[2*np+1][0], bf[2*np+1][1],
                      baddr + (uint32_t)(np * 16 * STH + kk) * 2u);
            #pragma unroll
            for (int m = 0; m < 4; m++)
                #pragma unroll
                for (int n = 0; n < 8; n++)
                    mma_f16(acc[m][n][0], acc[m][n][1], acc[m][n][2], acc[m][n][3],
                            af[m][0], af[m][1], af[m][2], af[m][3],
                            bf[n][0], bf[n][1]);
        }
        __syncthreads();
    }

    #pragma unroll
    for (int m = 0; m < 4; m++) {
        const long row0 = m0 + wm + m * 16 + g;
        #pragma unroll
        for (int n = 0; n < 8; n++) {
            const int col = n0 + wn + n * 8 + 2 * t;
            if constexpr (OM == 2) {
                __half* Cb = (__half*)Cv + (long)z * sC;
                *(__half2*)(Cb + row0 * N + col) =
                    __floats2half2_rn(acc[m][n][0], acc[m][n][1]);
                *(__half2*)(Cb + (row0 + 8) * N + col) =
                    __floats2half2_rn(acc[m][n][2], acc[m][n][3]);
            } else if constexpr (OM == 1) {
                float* Cb = (float*)Cv + (long)z * sC;
                *(float2*)(Cb + row0 * N + col) =
                    make_float2(f2tf32f(acc[m][n][0]), f2tf32f(acc[m][n][1]));
                *(float2*)(Cb + (row0 + 8) * N + col) =
                    make_float2(f2tf32f(acc[m][n][2]), f2tf32f(acc[m][n][3]));
            } else {
                float* Cb = (float*)Cv + (long)z * sC;
                *(float2*)(Cb + row0 * N + col)       = make_float2(acc[m][n][0], acc[m][n][1]);
                *(float2*)(Cb + (row0 + 8) * N + col) = make_float2(acc[m][n][2], acc[m][n][3]);
            }
        }
    }
}

// ---------------- transpose [H, RKV, HDIM] -> [H, HDIM, RKV], fp16 on store ----------------
__global__ __launch_bounds__(256)
void transpose_up(const float* __restrict__ in, __half* __restrict__ out)
{
    __shared__ float t[32][33];
    const int h = blockIdx.z;
    const int r0 = blockIdx.y * 32;   // RKV dim
    const int c0 = blockIdx.x * 32;   // HDIM dim
    const int tx = threadIdx.x & 31, ty0 = threadIdx.x >> 5;
    const float* ip = in + (long)h * RKV * HDIM;
    __half* op = out + (long)h * RKV * HDIM;
    #pragma unroll
    for (int r = 0; r < 4; r++) {
        int ty = ty0 + r * 8;
        t[ty][tx] = ip[(long)(r0 + ty) * HDIM + c0 + tx];
    }
    __syncthreads();
    #pragma unroll
    for (int r = 0; r < 4; r++) {
        int ty = ty0 + r * 8;
        op[(long)(c0 + ty) * RKV + r0 + tx] = __float2half_rn(t[tx][ty]);
    }
}

// ---------------- tensor-core flash attention v2 (tf32 mma, ALiBi + causal) ----------------
// BM=128, BN=64, d=128; 8 warps, warp-local softmax; K double-buffered, V single-buffered.
// Output written as fp16 (consumed by the fp16 Wo GEMM). Heavy q-tiles scheduled first.
#define FQS 132
#define FVS 136
#define FPS 68
#define F2_KOFF  (128*FQS)
#define F2_VOFF  (F2_KOFF + 2*64*FQS)
#define F2_POFF  (F2_VOFF + 64*FVS)
#define FLASH_SMEM_WORDS (F2_POFF + 128*FPS)
#define FLASH_SMEM_BYTES (FLASH_SMEM_WORDS * 4)  // 204800 B

__global__ __launch_bounds__(256)
void flash_tc(const float* __restrict__ Q, const float* __restrict__ Kg,
              const float* __restrict__ Vg, __half* __restrict__ O)
{
    extern __shared__ uint32_t sm[];
    const uint32_t sbase = smem_u32(sm);
    uint32_t* Qs = sm;                              // [128][132]
    uint32_t* Ps = sm + F2_POFF;                    // [128][68] tf32

    const int bh = blockIdx.y;
    const int b  = bh >> 4, h = bh & 15;
    const int qt = gridDim.x - 1 - blockIdx.x;      // heavy tiles first
    const int q0 = qt * 128;
    const int tid = threadIdx.x;
    const int wid = tid >> 5, lane = tid & 31;
    const int g = lane >> 2, t = lane & 3;

    const float slope = exp2f(-0.5f * (float)(h + 1));
    const float scale = 0.08838834764831843f;

    const float* Qbase = Q  + ((long)(b*SEQ + q0)) * DMODEL + h*HDIM;
    const float* Kbase = Kg + ((long)(b*NHEAD + h)) * SEQ * HDIM;
    const float* Vbase = Vg + ((long)(b*NHEAD + h)) * SEQ * HDIM;

    auto issueK = [&](int k0, int buf) {
        const uint32_t base = sbase + (uint32_t)(F2_KOFF + buf * 64 * FQS) * 4u;
        #pragma unroll
        for (int p = 0; p < 8; p++) {
            int idx = tid + p*256;
            int row = idx >> 5, c4 = (idx & 31) << 2;
            cp16(base + (uint32_t)(row*FQS + c4)*4u, Kbase + (long)(k0+row)*HDIM + c4);
        }
        CP_COMMIT();
    };
    auto issueV = [&](int k0) {
        const uint32_t base = sbase + (uint32_t)F2_VOFF * 4u;
        #pragma unroll
        for (int p = 0; p < 8; p++) {
            int idx = tid + p*256;
            int row = idx >> 5, c4 = (idx & 31) << 2;
            cp16(base + (uint32_t)(row*FVS + c4)*4u, Vbase + (long)(k0+row)*HDIM + c4);
        }
        CP_COMMIT();
    };

    // prologue group: Q tile (128x128) + K0
    #pragma unroll
    for (int p = 0; p < 16; p++) {
        int idx = tid + p*256;
        int row = idx >> 5, c4 = (idx & 31) << 2;
        cp16(sbase + (uint32_t)(row*FQS + c4)*4u, Qbase + (long)row*DMODEL + c4);
    }
    {
        const uint32_t base = sbase + (uint32_t)F2_KOFF * 4u;
        #pragma unroll
        for (int p = 0; p < 8; p++) {
            int idx = tid + p*256;
            int row = idx >> 5, c4 = (idx & 31) << 2;
            cp16(base + (uint32_t)(row*FQS + c4)*4u, Kbase + (long)row*HDIM + c4);
        }
        CP_COMMIT();
    }

    const int r0 = wid*16 + g, r1 = r0 + 8;
    const int qi0 = q0 + r0, qi1 = q0 + r1;

    float o[16][4];
    #pragma unroll
    for (int n = 0; n < 16; n++)
        #pragma unroll
        for (int r = 0; r < 4; r++) o[n][r] = 0.f;
    float m0 = -INFINITY, m1 = -INFINITY, l0 = 0.f, l1 = 0.f;

    const int ktmax = 2*qt + 1;
    for (int kt = 0; kt <= ktmax; kt++) {
        const int k0 = kt * 64;
        __syncthreads();
        issueV(k0);
        if (kt < ktmax) { issueK(k0 + 64, (kt + 1) & 1); CP_WAIT_1(); }
        else            { CP_WAIT_0(); }
        __syncthreads();

        const uint32_t* Kb = sm + F2_KOFF + (size_t)(kt & 1) * (64 * FQS);
        const uint32_t* Vb = sm + F2_VOFF;

        // S = Q @ K^T  (warp tile 16x64: 8 n-subtiles)
        float s[8][4];
        #pragma unroll
        for (int n = 0; n < 8; n++)
            #pragma unroll
            for (int r = 0; r < 4; r++) s[n][r] = 0.f;
        #pragma unroll
        for (int ks = 0; ks < 16; ks++) {
            const int kk = ks * 8;
            uint32_t a0 = Qs[r0*FQS + kk + t];
            uint32_t a1 = Qs[r1*FQS + kk + t];
            uint32_t a2 = Qs[r0*FQS + kk + t + 4];
            uint32_t a3 = Qs[r1*FQS + kk + t + 4];
            #pragma unroll
            for (int n = 0; n < 8; n++) {
                const int nr = n*8 + g;
                uint32_t b0 = Kb[nr*FQS + kk + t];
                uint32_t b1 = Kb[nr*FQS + kk + t + 4];
                mma_tf32(s[n][0], s[n][1], s[n][2], s[n][3], a0, a1, a2, a3, b0, b1);
            }
        }

        // scale + ALiBi + causal; warp-local row max
        float rv0 = -INFINITY, rv1 = -INFINITY;
        #pragma unroll
        for (int n = 0; n < 8; n++) {
            const int kj = k0 + n*8 + 2*t;
            s[n][0] = (kj   <= qi0) ? fmaf(s[n][0], scale, -slope*(float)(qi0-kj))   : -INFINITY;
            s[n][1] = (kj+1 <= qi0) ? fmaf(s[n][1], scale, -slope*(float)(qi0-kj-1)) : -INFINITY;
            s[n][2] = (kj   <= qi1) ? fmaf(s[n][2], scale, -slope*(float)(qi1-kj))   : -INFINITY;
            s[n][3] = (kj+1 <= qi1) ? fmaf(s[n][3], scale, -slope*(float)(qi1-kj-1)) : -INFINITY;
            rv0 = fmaxf(rv0, fmaxf(s[n][0], s[n][1]));
            rv1 = fmaxf(rv1, fmaxf(s[n][2], s[n][3]));
        }
        rv0 = fmaxf(rv0, __shfl_xor_sync(0xffffffffu, rv0, 1));
        rv0 = fmaxf(rv0, __shfl_xor_sync(0xffffffffu, rv0, 2));
        rv1 = fmaxf(rv1, __shfl_xor_sync(0xffffffffu, rv1, 1));
        rv1 = fmaxf(rv1, __shfl_xor_sync(0xffffffffu, rv1, 2));
        const float m0n = fmaxf(m0, rv0), m1n = fmaxf(m1, rv1);
        const float al0 = __expf(m0 - m0n), al1 = __expf(m1 - m1n);
        m0 = m0n; m1 = m1n;
        float rs0 = 0.f, rs1 = 0.f;
        #pragma unroll
        for (int n = 0; n < 8; n++) {
            float p00 = __expf(s[n][0] - m0n), p01 = __expf(s[n][1] - m0n);
            float p10 = __expf(s[n][2] - m1n), p11 = __expf(s[n][3] - m1n);
            rs0 += p00 + p01; rs1 += p10 + p11;
            const int cn = n*8 + 2*t;
            Ps[r0*FPS + cn] = f2tf32(p00); Ps[r0*FPS + cn + 1] = f2tf32(p01);
            Ps[r1*FPS + cn] = f2tf32(p10); Ps[r1*FPS + cn + 1] = f2tf32(p11);
        }
        rs0 += __shfl_xor_sync(0xffffffffu, rs0, 1);
        rs0 += __shfl_xor_sync(0xffffffffu, rs0, 2);
        rs1 += __shfl_xor_sync(0xffffffffu, rs1, 1);
        rs1 += __shfl_xor_sync(0xffffffffu, rs1, 2);
        l0 = l0 * al0 + rs0; l1 = l1 * al1 + rs1;
        #pragma unroll
        for (int n = 0; n < 16; n++) {
            o[n][0] *= al0; o[n][1] *= al0; o[n][2] *= al1; o[n][3] *= al1;
        }
        __syncwarp();

        // O += P @ V  (warp tile 16x128: 16 d-subtiles)
        #pragma unroll
        for (int ks = 0; ks < 8; ks++) {
            const int kk = ks * 8;
            uint32_t a0 = Ps[r0*FPS + kk + t];
            uint32_t a1 = Ps[r1*FPS + kk + t];
            uint32_t a2 = Ps[r0*FPS + kk + t + 4];
            uint32_t a3 = Ps[r1*FPS + kk + t + 4];
            #pragma unroll
            for (int n = 0; n < 16; n++) {
                const int col = n*8 + g;
                uint32_t b0 = Vb[(kk + t)*FVS + col];
                uint32_t b1 = Vb[(kk + t + 4)*FVS + col];
                mma_tf32(o[n][0], o[n][1], o[n][2], o[n][3], a0, a1, a2, a3, b0, b1);
            }
        }
    }

    // normalize + fp16 store O[b, q, h*128 + col]
    const float inv0 = 1.f / l0, inv1 = 1.f / l1;
    const long row0 = (long)(b*SEQ + q0 + r0);
    const long row1 = (long)(b*SEQ + q0 + r1);
    #pragma unroll
    for (int n = 0; n < 16; n++) {
        const int col = h*HDIM + n*8 + 2*t;
        *(__half2*)(O + row0*DMODEL + col) = __floats2half2_rn(o[n][0]*inv0, o[n][1]*inv0);
        *(__half2*)(O + row1*DMODEL + col) = __floats2half2_rn(o[n][2]*inv1, o[n][3]*inv1);
    }
}

// ---------------- launch ----------------
extern "C" void kernel_launch(void* const* d_in, const int* in_sizes, int n_in,
                              void* d_out, int out_size)
{
    const float* X        = (const float*)d_in[0];
    const float* Wq_down  = (const float*)d_in[1];   // [1536, 2048]
    const float* Wq_up    = (const float*)d_in[2];   // [2048, 1536]
    const float* Wkv_down = (const float*)d_in[3];   // [512, 2048]
    const float* k_up     = (const float*)d_in[4];   // [16, 512, 128]
    const float* v_up     = (const float*)d_in[5];   // [16, 512, 128]
    const float* Wo       = (const float*)d_in[6];   // [2048, 2048]
    float* out = (float*)d_out;

    __half *xq, *c, *ob, *kuT, *vuT, *xr, *wqdr, *wqur, *wkdr, *wor;
    float *q, *kb, *vb;
    cudaGetSymbolAddress((void**)&xq,  g_xq);
    cudaGetSymbolAddress((void**)&q,   g_q);
    cudaGetSymbolAddress((void**)&c,   g_c);
    cudaGetSymbolAddress((void**)&kb,  g_k);
    cudaGetSymbolAddress((void**)&vb,  g_v);
    cudaGetSymbolAddress((void**)&ob,  g_o);
    cudaGetSymbolAddress((void**)&kuT, g_kuT);
    cudaGetSymbolAddress((void**)&vuT, g_vuT);
    cudaGetSymbolAddress((void**)&xr,   g_xr);
    cudaGetSymbolAddress((void**)&wqdr, g_wqdr);
    cudaGetSymbolAddress((void**)&wqur, g_wqur);
    cudaGetSymbolAddress((void**)&wkdr, g_wkdr);
    cudaGetSymbolAddress((void**)&wor,  g_wor);

    cudaFuncSetAttribute(gemm_tc<0>, cudaFuncAttributeMaxDynamicSharedMemorySize, GEMM_SMEM_BYTES);
    cudaFuncSetAttribute(gemm_tc<1>, cudaFuncAttributeMaxDynamicSharedMemorySize, GEMM_SMEM_BYTES);
    cudaFuncSetAttribute(gemm_tc<2>, cudaFuncAttributeMaxDynamicSharedMemorySize, GEMM_SMEM_BYTES);
    cudaFuncSetAttribute(flash_tc,
                         cudaFuncAttributeMaxDynamicSharedMemorySize, FLASH_SMEM_BYTES);

    dim3 blk(256);
    dim3 blkG(128);
    const int ZBIG = 1 << 30;

    // 0) fp16-round all raw GEMM inputs (one-time copies)
    round_half<<<512, blk>>>(X,        xr,   (long)MTOT*DMODEL/4);
    round_half<<<512, blk>>>(Wq_down,  wqdr, (long)RQ*DMODEL/4);
    round_half<<<512, blk>>>(Wq_up,    wqur, (long)DMODEL*RQ/4);
    round_half<<<512, blk>>>(Wkv_down, wkdr, (long)RKV*DMODEL/4);
    round_half<<<512, blk>>>(Wo,       wor,  (long)DMODEL*DMODEL/4);
    transpose_up<<<dim3(HDIM/32, RKV/32, NHEAD), blk>>>(k_up, kuT);
    transpose_up<<<dim3(HDIM/32, RKV/32, NHEAD), blk>>>(v_up, vuT);

    // 1) Xq = X @ Wq_down^T : [4096,1536] fp16 out (feeds GEMM 2)
    gemm_tc<2><<<dim3(RQ/128, MTOT/128, 1), blkG, GEMM_SMEM_BYTES>>>(
        xr, wqdr, xq, wqdr, xq, ZBIG, MTOT, RQ, DMODEL, 0, 0, 0, 1);
    // 2) Q = Xq @ Wq_up^T : [4096,2048] fp32 tf32-rounded (feeds flash)
    gemm_tc<1><<<dim3(DMODEL/128, MTOT/128, 1), blkG, GEMM_SMEM_BYTES>>>(
        xq, wqur, q, wqur, q, ZBIG, MTOT, DMODEL, RQ, 0, 0, 0, 1);
    // 3) C = X @ Wkv_down^T : [4096,512] fp16 out (feeds merged K/V GEMM)
    gemm_tc<2><<<dim3(RKV/128, MTOT/128, 1), blkG, GEMM_SMEM_BYTES>>>(
        xr, wkdr, c, wkdr, c, ZBIG, MTOT, RKV, DMODEL, 0, 0, 0, 1);
    // 4+5) merged K and V up-projections: z<32 -> K, z>=32 -> V; fp32 tf32-rounded out
    gemm_tc<1><<<dim3(1, SEQ/128, 2*BATCH*NHEAD), blkG, GEMM_SMEM_BYTES>>>(
        c, kuT, kb, vuT, vb, BATCH*NHEAD, SEQ, HDIM, RKV,
        (long)SEQ*RKV, (long)HDIM*RKV, (long)SEQ*HDIM, NHEAD);
    // 6) tensor-core causal+ALiBi flash attention (BM=128) -> ob (fp16)
    flash_tc<<<dim3(SEQ/128, BATCH*NHEAD), blk, FLASH_SMEM_BYTES>>>(q, kb, vb, ob);
    // 7) out = ob @ Wo^T : [4096,2048] fp32 final output
    gemm_tc<0><<<dim3(DMODEL/128, MTOT/128, 1), blkG, GEMM_SMEM_BYTES>>>(
        ob, wor, out, wor, out, ZBIG, MTOT, DMODEL, DMODEL, 0, 0, 0, 1);
}